// round 1
// baseline (speedup 1.0000x reference)
#include <cuda_runtime.h>
#include <cstdint>

#define XN (64*512*28*28)      // 25,690,112
#define HN (64*1024*28*28)     // 51,380,224

__device__ float g_A[XN];
__device__ float g_C[XN];
__device__ float g_H[HN];

__device__ __forceinline__ float hswish(float v){
    float r = v + 3.0f;
    r = fminf(fmaxf(r, 0.0f), 6.0f);
    return v * r * (1.0f/6.0f);
}

// ---------------------------------------------------------------------------
// depthwise 3x3 conv (SAME) + residual:  out = x + (dwconv(x) + b)
// ---------------------------------------------------------------------------
__global__ __launch_bounds__(256) void dw3_res(const float* __restrict__ x,
        const float* __restrict__ w, const float* __restrict__ b,
        float* __restrict__ out){
    int idx = blockIdx.x*256 + threadIdx.x;           // grid sized exactly XN/256
    int hw = idx % 784;
    int c  = (idx/784) & 511;
    int h  = hw/28, wc = hw%28;
    const float* xp = x + (idx - hw);                 // base of this (b,c) plane
    const float* wp = w + c*9;
    float acc = b[c];
    #pragma unroll
    for(int dy=0;dy<3;dy++){
        int hh = h + dy - 1;
        if(hh<0||hh>=28) continue;
        #pragma unroll
        for(int dx=0;dx<3;dx++){
            int ww = wc + dx - 1;
            if(ww<0||ww>=28) continue;
            acc += wp[dy*3+dx]*xp[hh*28+ww];
        }
    }
    out[idx] = x[idx] + acc;
}

// ---------------------------------------------------------------------------
// Tiled SGEMM: Out[bz][m][n] = epi( sum_k W[m][k]*In[bz][k][n] + bias[m] )
// BM=128, BN=64, BK=16, 256 threads, 8x4 per-thread microtile.
// MODE 0: Out = hswish(acc+bias)
// MODE 1: Out[idx] = Res[idx] + acc+bias          (same [bz][M][N] layout)
// MODE 2: proj: bz = window id, n = token; window-merge index, += residual
// ---------------------------------------------------------------------------
template<int MODE>
__global__ __launch_bounds__(256) void sgemm_k(
        const float* __restrict__ Wm, const float* __restrict__ In,
        const float* __restrict__ bias, const float* __restrict__ Res,
        float* __restrict__ Out, int M, int N, int K)
{
    __shared__ float As[16][128];
    __shared__ float Bs[16][64];
    const int tid = threadIdx.x;
    const int bn0 = blockIdx.x*64, bm0 = blockIdx.y*128;
    const int bz  = blockIdx.z;
    const float* Inb = In + (size_t)bz*K*N;
    const int ty = tid>>4, tx = tid&15;

    float acc[8][4];
    #pragma unroll
    for(int i=0;i<8;i++)
        #pragma unroll
        for(int j=0;j<4;j++) acc[i][j]=0.f;

    const int wm  = tid>>1;          // 0..127
    const int wk8 = (tid&1)*8;       // 0 or 8
    const int bk  = ty;              // 0..15
    const int bnl = tx*4;            // 0..60

    for(int k0=0;k0<K;k0+=16){
        // A tile (transposed into As[k][m])
        const float* wp = Wm + (size_t)(bm0+wm)*K + k0 + wk8;
        float4 a0 = *(const float4*)wp;
        float4 a1 = *(const float4*)(wp+4);
        As[wk8+0][wm]=a0.x; As[wk8+1][wm]=a0.y; As[wk8+2][wm]=a0.z; As[wk8+3][wm]=a0.w;
        As[wk8+4][wm]=a1.x; As[wk8+5][wm]=a1.y; As[wk8+6][wm]=a1.z; As[wk8+7][wm]=a1.w;
        // B tile
        {
            int gn = bn0 + bnl;
            const float* ip = Inb + (size_t)(k0+bk)*N + gn;
            if(((N&3)==0) && (gn+3 < N)){
                float4 v = *(const float4*)ip;
                Bs[bk][bnl]=v.x; Bs[bk][bnl+1]=v.y; Bs[bk][bnl+2]=v.z; Bs[bk][bnl+3]=v.w;
            } else {
                #pragma unroll
                for(int j=0;j<4;j++) Bs[bk][bnl+j] = (gn+j<N) ? ip[j] : 0.f;
            }
        }
        __syncthreads();
        #pragma unroll
        for(int kk=0;kk<16;kk++){
            float4 av0 = *(const float4*)&As[kk][ty*8];
            float4 av1 = *(const float4*)&As[kk][ty*8+4];
            float4 bv  = *(const float4*)&Bs[kk][tx*4];
            float aR[8] = {av0.x,av0.y,av0.z,av0.w,av1.x,av1.y,av1.z,av1.w};
            float bR[4] = {bv.x,bv.y,bv.z,bv.w};
            #pragma unroll
            for(int i=0;i<8;i++)
                #pragma unroll
                for(int j=0;j<4;j++) acc[i][j] += aR[i]*bR[j];
        }
        __syncthreads();
    }

    #pragma unroll
    for(int i=0;i<8;i++){
        int m = bm0 + ty*8 + i;
        float bv = bias[m];
        #pragma unroll
        for(int j=0;j<4;j++){
            int n = bn0 + tx*4 + j;
            if(n>=N) continue;
            float v = acc[i][j] + bv;
            if(MODE==0){
                Out[((size_t)bz*M + m)*N + n] = hswish(v);
            } else if(MODE==1){
                size_t idx = ((size_t)bz*M + m)*N + n;
                Out[idx] = Res[idx] + v;
            } else {
                int b  = bz>>4, wi=(bz>>2)&3, wj=bz&3;
                int r  = n/7, c = n-(n/7)*7;
                size_t idx = (((size_t)b*512 + m)*28 + wi*7+r)*28 + (wj*7+c);
                Out[idx] = Res[idx] + v;
            }
        }
    }
}

// ---------------------------------------------------------------------------
// Cascaded window attention. One block (256 thr) per window (1024 windows).
// Entire 8-head cascade held in shared memory; writes hswish(concat) to C
// laid out [window][512][49].
// ---------------------------------------------------------------------------
#define AP 52   // smem row pitch (floats)
#define ATT_SMEM_FLOATS ((64+96+16+49)*AP + 96*64 + 128)
#define ATT_SMEM_BYTES  (ATT_SMEM_FLOATS*4)

__global__ __launch_bounds__(256) void attn_kernel(
    const float* __restrict__ A,
    const float* __restrict__ qkvw, const float* __restrict__ qkvb,
    const float* __restrict__ w7, const float* __restrict__ b7,
    const float* __restrict__ w5, const float* __restrict__ b5,
    const float* __restrict__ w3, const float* __restrict__ b3,
    const float* __restrict__ abias,
    float* __restrict__ C)
{
    extern __shared__ float sm[];
    float* sp  = sm;                  // [64][AP]
    float* y   = sp  + 64*AP;         // [96][AP]  (q:0..15, k:16..31, v:32..95)
    float* qc  = y   + 96*AP;         // [16][AP]
    float* att = qc  + 16*AP;         // [49][AP]
    float* qw  = att + 49*AP;         // [96][64]
    float* qb  = qw  + 96*64;         // [96]

    const int w = blockIdx.x, tid = threadIdx.x;
    const int b = w>>4, wi=(w>>2)&3, wj=w&3;
    const float* base = A + (size_t)b*512*784 + (wi*7)*28 + wj*7;

    for(int hd=0; hd<8; hd++){
        // qkv weights for this head
        for(int i=tid;i<96*64;i+=256) qw[i] = qkvw[hd*96*64 + i];
        if(tid<96) qb[tid] = qkvb[hd*96 + tid];
        // cascade accumulate input slice
        for(int i=tid;i<64*49;i+=256){
            int cch = i/49, t = i - cch*49;
            int r = t/7, cc = t - r*7;
            float v = base[(size_t)(hd*64+cch)*784 + r*28 + cc];
            if(hd==0) sp[cch*AP+t] = v; else sp[cch*AP+t] += v;
        }
        __syncthreads();

        // y = qw @ sp + qb   (96x49, K=64), 4x4 microtiles
        for(int u=tid; u<24*13; u+=256){
            int o0 = (u/13)*4, t0 = (u%13)*4;
            float acc[4][4];
            #pragma unroll
            for(int i=0;i<4;i++){ float bb=qb[o0+i];
                #pragma unroll
                for(int j=0;j<4;j++) acc[i][j]=bb; }
            for(int c=0;c<64;c++){
                float s0=sp[c*AP+t0], s1=sp[c*AP+t0+1], s2=sp[c*AP+t0+2], s3=sp[c*AP+t0+3];
                #pragma unroll
                for(int i=0;i<4;i++){
                    float wv = qw[(o0+i)*64+c];
                    acc[i][0]+=wv*s0; acc[i][1]+=wv*s1; acc[i][2]+=wv*s2; acc[i][3]+=wv*s3;
                }
            }
            #pragma unroll
            for(int i=0;i<4;i++)
                #pragma unroll
                for(int j=0;j<4;j++)
                    if(t0+j<49) y[(o0+i)*AP + t0+j] = acc[i][j];
        }
        __syncthreads();

        // depthwise conv on q (rows 0..15 of y), kernel size per head
        {
            int ks = (hd==0)?7:((hd==1)?5:3);
            int pad = ks>>1;
            const float* cw; const float* cb;
            if(hd==0){ cw=w7; cb=b7; }
            else if(hd==1){ cw=w5; cb=b5; }
            else { cw = w3 + (hd-2)*16*9; cb = b3 + (hd-2)*16; }
            for(int i=tid;i<16*49;i+=256){
                int ch=i/49, t=i-ch*49; int r=t/7, cc=t-r*7;
                float acc = cb[ch];
                const float* wp = cw + ch*ks*ks;
                for(int dy=0;dy<ks;dy++){
                    int rr = r+dy-pad; if(rr<0||rr>=7) continue;
                    for(int dx=0;dx<ks;dx++){
                        int c2 = cc+dx-pad; if(c2<0||c2>=7) continue;
                        acc += wp[dy*ks+dx]*y[ch*AP + rr*7+c2];
                    }
                }
                qc[ch*AP+t]=acc;
            }
        }
        __syncthreads();

        // attn[n][m] = scale * q.k + bias
        for(int i=tid;i<49*49;i+=256){
            int n=i/49, m=i-n*49;
            float acc=0.f;
            #pragma unroll
            for(int c=0;c<16;c++) acc += qc[c*AP+n]*y[(16+c)*AP+m];
            int r1=n/7, c1=n-(n/7)*7, r2=m/7, c2=m-(m/7)*7;
            int dr=r1-r2; if(dr<0)dr=-dr;
            int dc=c1-c2; if(dc<0)dc=-dc;
            att[n*AP+m] = acc*0.25f + abias[hd*49 + dr*7+dc];
        }
        __syncthreads();

        // row softmax (over m)
        if(tid<49){
            float mx=-1e30f;
            for(int m=0;m<49;m++) mx = fmaxf(mx, att[tid*AP+m]);
            float s=0.f;
            for(int m=0;m<49;m++){ float e=__expf(att[tid*AP+m]-mx); att[tid*AP+m]=e; s+=e; }
            float inv = 1.f/s;
            for(int m=0;m<49;m++) att[tid*AP+m]*=inv;
        }
        __syncthreads();

        // sp_new[d][t] = sum_m v[d][m]*att[t][m]; write hswish to C
        float* Cw = C + ((size_t)w*512 + hd*64)*49;
        for(int u=tid; u<16*13; u+=256){
            int d0=(u/13)*4, t0=(u%13)*4;
            float acc[4][4] = {};
            for(int m=0;m<49;m++){
                float a0=att[(t0+0)*AP+m], a1=att[(t0+1)*AP+m];
                float a2=att[(t0+2)*AP+m], a3=att[(t0+3)*AP+m];
                #pragma unroll
                for(int i=0;i<4;i++){
                    float vv = y[(32+d0+i)*AP+m];
                    acc[i][0]+=vv*a0; acc[i][1]+=vv*a1; acc[i][2]+=vv*a2; acc[i][3]+=vv*a3;
                }
            }
            #pragma unroll
            for(int i=0;i<4;i++)
                #pragma unroll
                for(int j=0;j<4;j++)
                    if(t0+j<49){
                        sp[(d0+i)*AP + t0+j] = acc[i][j];
                        Cw[(d0+i)*49 + t0+j] = hswish(acc[i][j]);
                    }
        }
        __syncthreads();
    }
}

// ---------------------------------------------------------------------------
extern "C" void kernel_launch(void* const* d_in, const int* in_sizes, int n_in,
                              void* d_out, int out_size) {
    const float* x     = (const float*)d_in[0];
    const float* dw0w  = (const float*)d_in[1];
    const float* dw0b  = (const float*)d_in[2];
    const float* f0w1  = (const float*)d_in[3];
    const float* f0b1  = (const float*)d_in[4];
    const float* f0w2  = (const float*)d_in[5];
    const float* f0b2  = (const float*)d_in[6];
    const float* qkvw  = (const float*)d_in[7];
    const float* qkvb  = (const float*)d_in[8];
    const float* w7    = (const float*)d_in[9];
    const float* b7    = (const float*)d_in[10];
    const float* w5    = (const float*)d_in[11];
    const float* b5    = (const float*)d_in[12];
    const float* w3    = (const float*)d_in[13];
    const float* b3    = (const float*)d_in[14];
    const float* ab    = (const float*)d_in[15];
    const float* pw_   = (const float*)d_in[16];
    const float* pb    = (const float*)d_in[17];
    const float* dw1w  = (const float*)d_in[18];
    const float* dw1b  = (const float*)d_in[19];
    const float* f1w1  = (const float*)d_in[20];
    const float* f1b1  = (const float*)d_in[21];
    const float* f1w2  = (const float*)d_in[22];
    const float* f1b2  = (const float*)d_in[23];
    float* out = (float*)d_out;

    float *A, *C, *H;
    cudaGetSymbolAddress((void**)&A, g_A);
    cudaGetSymbolAddress((void**)&C, g_C);
    cudaGetSymbolAddress((void**)&H, g_H);

    cudaFuncSetAttribute(attn_kernel,
        cudaFuncAttributeMaxDynamicSharedMemorySize, ATT_SMEM_BYTES);

    // 1. A = x + dw0(x)
    dw3_res<<<XN/256, 256>>>(x, dw0w, dw0b, A);
    // 2. H = hswish(W1 @ A + b1)
    sgemm_k<0><<<dim3(13,8,64), 256>>>(f0w1, A, f0b1, nullptr, H, 1024, 784, 512);
    // 3. A = A + (W2 @ H + b2)          (in-place residual)
    sgemm_k<1><<<dim3(13,4,64), 256>>>(f0w2, H, f0b2, A, A, 512, 784, 1024);
    // 4. cascaded window attention -> C = hswish(concat)
    attn_kernel<<<1024, 256, ATT_SMEM_BYTES>>>(A, qkvw, qkvb, w7,b7, w5,b5, w3,b3, ab, C);
    // 5. A = A + merge(proj_w @ C + proj_b)   (fused merge+residual, in-place)
    sgemm_k<2><<<dim3(1,4,1024), 256>>>(pw_, C, pb, A, A, 512, 49, 512);
    // 6. C = A + dw1(A)
    dw3_res<<<XN/256, 256>>>(A, dw1w, dw1b, C);
    // 7. H = hswish(W1' @ C + b1')
    sgemm_k<0><<<dim3(13,8,64), 256>>>(f1w1, C, f1b1, nullptr, H, 1024, 784, 512);
    // 8. out = C + (W2' @ H + b2')
    sgemm_k<1><<<dim3(13,4,64), 256>>>(f1w2, H, f1b2, C, out, 512, 784, 1024);
}

// round 2
// speedup vs baseline: 1.4632x; 1.4632x over previous
#include <cuda_runtime.h>
#include <cstdint>

#define XN (64*512*28*28)      // 25,690,112  = 512 x 50176
#define HN (64*1024*28*28)     // 51,380,224  = 1024 x 50176
#define NTOT 50176

__device__ float g_A[XN];
__device__ float g_C[XN];
__device__ float g_H[HN];

__device__ __forceinline__ float hswish(float v){
    float r = v + 3.0f;
    r = fminf(fmaxf(r, 0.0f), 6.0f);
    return v * r * (1.0f/6.0f);
}

__device__ __forceinline__ float to_tf32(float x){
    uint32_t u;
    asm("cvt.rna.tf32.f32 %0, %1;" : "=r"(u) : "f"(x));
    return __uint_as_float(u);
}

__device__ __forceinline__ void mma_tf32(float* d, const uint32_t* a, const uint32_t* b){
    asm volatile("mma.sync.aligned.m16n8k8.row.col.f32.tf32.tf32.f32 "
        "{%0,%1,%2,%3}, {%4,%5,%6,%7}, {%8,%9}, {%0,%1,%2,%3};"
        : "+f"(d[0]), "+f"(d[1]), "+f"(d[2]), "+f"(d[3])
        : "r"(a[0]), "r"(a[1]), "r"(a[2]), "r"(a[3]), "r"(b[0]), "r"(b[1]));
}

// ---------------------------------------------------------------------------
// depthwise 3x3 + residual. Activations channel-major: plane p = c*64 + b.
// IN_STD=1: input x is standard [B][C][HW]; IN_STD=0: input is channel-major.
// Output always channel-major.
// ---------------------------------------------------------------------------
template<int IN_STD>
__global__ __launch_bounds__(256) void dw3_res(const float* __restrict__ x,
        const float* __restrict__ w, const float* __restrict__ b,
        float* __restrict__ out){
    int idx = blockIdx.x*256 + threadIdx.x;
    int hw = idx % 784;
    int p  = idx / 784;               // p = c*64 + bimg
    int c  = p >> 6;
    int h  = hw/28, wc = hw%28;
    const float* xp;
    if(IN_STD){
        int bimg = p & 63;
        xp = x + ((size_t)bimg*512 + c)*784;
    } else {
        xp = x + (size_t)p*784;
    }
    const float* wp = w + c*9;
    float acc = b[c];
    #pragma unroll
    for(int dy=0;dy<3;dy++){
        int hh = h + dy - 1;
        if(hh<0||hh>=28) continue;
        #pragma unroll
        for(int dx=0;dx<3;dx++){
            int ww = wc + dx - 1;
            if(ww<0||ww>=28) continue;
            acc += wp[dy*3+dx]*xp[hh*28+ww];
        }
    }
    out[(size_t)p*784 + hw] = xp[hw] + acc;
}

// ---------------------------------------------------------------------------
// TF32 tensor-core GEMM: Out[m][n] = epi( sum_k W[m][k] * In[k][n] + bias[m] )
// Block tile 256(M) x 64(N), BK=16, 256 threads = 8 warps (4m x 2n),
// warp tile 64x32 (4 m-frags x 4 n-frags of m16n8k8).
// MODE 0: Out[m*Nn+n]  = hswish(v)
// MODE 1: Out[m*Nn+n]  = Res[m*Nn+n] + v
// MODE 2: proj: n -> (win,t) -> pixel; Out[A2 idx] = Res[same] + v
// MODE 3: final: n -> (b,hw); Out std layout = Res[m*Nn+n] + v
// Requirements: M%256==0, Nn%64==0, K%16==0 (all hold here).
// ---------------------------------------------------------------------------
template<int MODE>
__global__ __launch_bounds__(256) void tgemm(
        const float* __restrict__ Wm, const float* __restrict__ In,
        const float* __restrict__ bias, const float* __restrict__ Res,
        float* __restrict__ Out, int K, int Nn)
{
    __shared__ float As[16][264];   // [k][m], pitch%32 == 8 -> conflict-free frags
    __shared__ float Bs[16][72];    // [k][n]
    const int tid  = threadIdx.x;
    const int lane = tid & 31, wid = tid >> 5;
    const int bn0  = blockIdx.x*64;
    const int bm0  = blockIdx.y*256;
    const int wm0  = (wid>>1)*64, wn0 = (wid&1)*32;
    const int r = lane>>2, c = lane&3;

    float acc[4][4][4];
    #pragma unroll
    for(int i=0;i<4;i++)
        #pragma unroll
        for(int j=0;j<4;j++)
            #pragma unroll
            for(int q=0;q<4;q++) acc[i][j][q]=0.f;

    const float* wrow = Wm + (size_t)(bm0 + tid)*K;
    const int bk = tid>>4, bn4 = (tid&15)*4;

    for(int k0=0; k0<K; k0+=16){
        // A tile: thread = one m row, 16 k values (4 float4), store transposed
        #pragma unroll
        for(int q=0;q<4;q++){
            float4 v = *(const float4*)(wrow + k0 + q*4);
            As[q*4+0][tid] = to_tf32(v.x);
            As[q*4+1][tid] = to_tf32(v.y);
            As[q*4+2][tid] = to_tf32(v.z);
            As[q*4+3][tid] = to_tf32(v.w);
        }
        // B tile: 16 rows x 64 cols, one float4 per thread
        {
            const float* ip = In + (size_t)(k0+bk)*Nn + bn0 + bn4;
            float4 v = *(const float4*)ip;
            float4 t4;
            t4.x = to_tf32(v.x); t4.y = to_tf32(v.y);
            t4.z = to_tf32(v.z); t4.w = to_tf32(v.w);
            *(float4*)&Bs[bk][bn4] = t4;
        }
        __syncthreads();
        #pragma unroll
        for(int kk=0; kk<16; kk+=8){
            uint32_t af[4][4], bf[4][2];
            #pragma unroll
            for(int mi=0;mi<4;mi++){
                int m = wm0 + mi*16 + r;
                af[mi][0] = __float_as_uint(As[kk+c  ][m  ]);
                af[mi][1] = __float_as_uint(As[kk+c  ][m+8]);
                af[mi][2] = __float_as_uint(As[kk+c+4][m  ]);
                af[mi][3] = __float_as_uint(As[kk+c+4][m+8]);
            }
            #pragma unroll
            for(int ni=0;ni<4;ni++){
                int n = wn0 + ni*8 + r;
                bf[ni][0] = __float_as_uint(Bs[kk+c  ][n]);
                bf[ni][1] = __float_as_uint(Bs[kk+c+4][n]);
            }
            #pragma unroll
            for(int mi=0;mi<4;mi++)
                #pragma unroll
                for(int ni=0;ni<4;ni++)
                    mma_tf32(acc[mi][ni], af[mi], bf[ni]);
        }
        __syncthreads();
    }

    // epilogue
    #pragma unroll
    for(int mi=0;mi<4;mi++){
        int mA = bm0 + wm0 + mi*16 + r;
        float bv0 = bias[mA], bv1 = bias[mA+8];
        #pragma unroll
        for(int ni=0;ni<4;ni++){
            int n = bn0 + wn0 + ni*8 + 2*c;
            #pragma unroll
            for(int half=0; half<2; half++){
                int m = mA + half*8;
                float v0 = acc[mi][ni][half*2+0] + (half? bv1:bv0);
                float v1 = acc[mi][ni][half*2+1] + (half? bv1:bv0);
                if(MODE==0){
                    size_t o = (size_t)m*Nn + n;
                    float2 w2; w2.x = hswish(v0); w2.y = hswish(v1);
                    *(float2*)(Out + o) = w2;
                } else if(MODE==1){
                    size_t o = (size_t)m*Nn + n;
                    float2 rv = *(const float2*)(Res + o);
                    float2 w2; w2.x = rv.x + v0; w2.y = rv.y + v1;
                    *(float2*)(Out + o) = w2;
                } else if(MODE==2){
                    #pragma unroll
                    for(int e=0;e<2;e++){
                        int nn = n+e; float v = e? v1:v0;
                        int win = nn/49, t = nn - win*49;
                        int bimg = win>>4, wi=(win>>2)&3, wj=win&3;
                        int rr = t/7, cc = t - rr*7;
                        size_t idx = ((size_t)m*64 + bimg)*784 + (wi*7+rr)*28 + wj*7+cc;
                        Out[idx] = Res[idx] + v;
                    }
                } else { // MODE 3
                    size_t ri = (size_t)m*Nn + n;
                    #pragma unroll
                    for(int e=0;e<2;e++){
                        int nn = n+e; float v = e? v1:v0;
                        int bimg = nn/784, hw = nn - bimg*784;
                        Out[(size_t)bimg*401408 + (size_t)m*784 + hw] = Res[ri+e] + v;
                    }
                }
            }
        }
    }
}

// ---------------------------------------------------------------------------
// Cascaded window attention (channel-major input, [C][win*49] output).
// ---------------------------------------------------------------------------
#define AP 52
#define SP_F   (64*AP)
#define Y_F    (80*AP)     // rows 0-15: q, rows 16-79: v
#define QC_F   (49*20)
#define KT_F   (49*20)
#define ATT_F  (49*AP)
#define QW_F   (96*64)
#define ATT_SMEM_FLOATS (SP_F + Y_F + QC_F + KT_F + ATT_F + QW_F + 96)
#define ATT_SMEM_BYTES  (ATT_SMEM_FLOATS*4)

__global__ __launch_bounds__(256) void attn_kernel(
    const float* __restrict__ A,
    const float* __restrict__ qkvw, const float* __restrict__ qkvb,
    const float* __restrict__ w7, const float* __restrict__ b7,
    const float* __restrict__ w5, const float* __restrict__ b5,
    const float* __restrict__ w3, const float* __restrict__ b3,
    const float* __restrict__ abias,
    float* __restrict__ C)
{
    extern __shared__ float sm[];
    float* sp  = sm;                 // [64][AP]
    float* y   = sp  + SP_F;         // [80][AP]
    float* qc2 = y   + Y_F;          // [49][20]
    float* kt  = qc2 + QC_F;         // [49][20]
    float* att = kt  + KT_F;         // [49][AP]
    float* qw  = att + ATT_F;        // [96][64]
    float* qb  = qw  + QW_F;         // [96]

    const int w = blockIdx.x, tid = threadIdx.x;
    const int bimg = w>>4, wi=(w>>2)&3, wj=w&3;
    const int off0 = (wi*7)*28 + wj*7;

    for(int hd=0; hd<8; hd++){
        for(int i=tid;i<96*64;i+=256) qw[i] = qkvw[hd*96*64 + i];
        if(tid<96) qb[tid] = qkvb[hd*96 + tid];
        for(int i=tid;i<64*49;i+=256){
            int cch = i/49, t = i - cch*49;
            int r = t/7, cc = t - r*7;
            float v = A[((size_t)(hd*64+cch)*64 + bimg)*784 + off0 + r*28 + cc];
            if(hd==0) sp[cch*AP+t] = v; else sp[cch*AP+t] += v;
        }
        __syncthreads();

        // y = qw @ sp + qb   (96x49, K=64), float4 LDS
        for(int u=tid; u<24*13; u+=256){
            int o0 = (u/13)*4, t0 = (u%13)*4;
            float acc[4][4];
            #pragma unroll
            for(int i=0;i<4;i++){ float bb=qb[o0+i];
                #pragma unroll
                for(int j=0;j<4;j++) acc[i][j]=bb; }
            for(int cI=0;cI<64;cI+=4){
                float4 s0=*(const float4*)&sp[(cI+0)*AP+t0];
                float4 s1=*(const float4*)&sp[(cI+1)*AP+t0];
                float4 s2=*(const float4*)&sp[(cI+2)*AP+t0];
                float4 s3=*(const float4*)&sp[(cI+3)*AP+t0];
                #pragma unroll
                for(int i=0;i<4;i++){
                    float4 qv = *(const float4*)&qw[(o0+i)*64+cI];
                    acc[i][0] += qv.x*s0.x + qv.y*s1.x + qv.z*s2.x + qv.w*s3.x;
                    acc[i][1] += qv.x*s0.y + qv.y*s1.y + qv.z*s2.y + qv.w*s3.y;
                    acc[i][2] += qv.x*s0.z + qv.y*s1.z + qv.z*s2.z + qv.w*s3.z;
                    acc[i][3] += qv.x*s0.w + qv.y*s1.w + qv.z*s2.w + qv.w*s3.w;
                }
            }
            #pragma unroll
            for(int i=0;i<4;i++)
                #pragma unroll
                for(int j=0;j<4;j++){
                    int o = o0+i, t = t0+j;
                    if(t<49){
                        float v = acc[i][j];
                        if(o<16)      y[o*AP+t] = v;
                        else if(o<32) kt[t*20 + (o-16)] = v;
                        else          y[(o-16)*AP+t] = v;
                    }
                }
        }
        __syncthreads();

        // depthwise conv on q -> qc2 [t][c]
        {
            int ks = (hd==0)?7:((hd==1)?5:3);
            int pad = ks>>1;
            const float* cw; const float* cb;
            if(hd==0){ cw=w7; cb=b7; }
            else if(hd==1){ cw=w5; cb=b5; }
            else { cw = w3 + (hd-2)*16*9; cb = b3 + (hd-2)*16; }
            for(int i=tid;i<16*49;i+=256){
                int ch=i/49, t=i-ch*49; int r=t/7, cc=t-r*7;
                float acc = cb[ch];
                const float* wp = cw + ch*ks*ks;
                for(int dy=0;dy<ks;dy++){
                    int rr = r+dy-pad; if(rr<0||rr>=7) continue;
                    for(int dx=0;dx<ks;dx++){
                        int c2 = cc+dx-pad; if(c2<0||c2>=7) continue;
                        acc += wp[dy*ks+dx]*y[ch*AP + rr*7+c2];
                    }
                }
                qc2[t*20+ch]=acc;
            }
        }
        __syncthreads();

        // attn[n][m] = scale * q.k + bias   (float4 over c)
        for(int i=tid;i<49*49;i+=256){
            int n=i/49, m=i-n*49;
            float acc=0.f;
            #pragma unroll
            for(int cI=0;cI<16;cI+=4){
                float4 qv=*(const float4*)&qc2[n*20+cI];
                float4 kv=*(const float4*)&kt[m*20+cI];
                acc += qv.x*kv.x+qv.y*kv.y+qv.z*kv.z+qv.w*kv.w;
            }
            int r1=n/7, c1=n-(n/7)*7, r2=m/7, c2=m-(m/7)*7;
            int dr=r1-r2; if(dr<0)dr=-dr;
            int dc=c1-c2; if(dc<0)dc=-dc;
            att[n*AP+m] = acc*0.25f + abias[hd*49 + dr*7+dc];
        }
        __syncthreads();

        if(tid<49){
            float mx=-1e30f;
            for(int m=0;m<49;m++) mx = fmaxf(mx, att[tid*AP+m]);
            float s=0.f;
            for(int m=0;m<49;m++){ float e=__expf(att[tid*AP+m]-mx); att[tid*AP+m]=e; s+=e; }
            float inv = 1.f/s;
            for(int m=0;m<49;m++) att[tid*AP+m]*=inv;
        }
        __syncthreads();

        // out[d][t] = sum_m v[d][m]*att[t][m]
        float* Cw = C + (size_t)(hd*64)*NTOT + w*49;
        for(int u=tid; u<16*13; u+=256){
            int d0=(u/13)*4, t0=(u%13)*4;
            float acc[4][4];
            #pragma unroll
            for(int i=0;i<4;i++)
                #pragma unroll
                for(int j=0;j<4;j++) acc[i][j]=0.f;
            for(int m=0;m<48;m+=4){
                float4 a0=*(const float4*)&att[(t0+0)*AP+m];
                float4 a1=*(const float4*)&att[(t0+1)*AP+m];
                float4 a2=*(const float4*)&att[(t0+2)*AP+m];
                float4 a3=*(const float4*)&att[(t0+3)*AP+m];
                #pragma unroll
                for(int i=0;i<4;i++){
                    float4 vv = *(const float4*)&y[(16+d0+i)*AP+m];
                    acc[i][0]+=vv.x*a0.x+vv.y*a0.y+vv.z*a0.z+vv.w*a0.w;
                    acc[i][1]+=vv.x*a1.x+vv.y*a1.y+vv.z*a1.z+vv.w*a1.w;
                    acc[i][2]+=vv.x*a2.x+vv.y*a2.y+vv.z*a2.z+vv.w*a2.w;
                    acc[i][3]+=vv.x*a3.x+vv.y*a3.y+vv.z*a3.z+vv.w*a3.w;
                }
            }
            { // tail m=48
                int m=48;
                #pragma unroll
                for(int i=0;i<4;i++){
                    float vv = y[(16+d0+i)*AP+m];
                    acc[i][0]+=vv*att[(t0+0)*AP+m];
                    acc[i][1]+=vv*att[(t0+1)*AP+m];
                    acc[i][2]+=vv*att[(t0+2)*AP+m];
                    acc[i][3]+=vv*att[(t0+3)*AP+m];
                }
            }
            #pragma unroll
            for(int i=0;i<4;i++)
                #pragma unroll
                for(int j=0;j<4;j++)
                    if(t0+j<49){
                        sp[(d0+i)*AP + t0+j] = acc[i][j];
                        Cw[(size_t)(d0+i)*NTOT + t0+j] = hswish(acc[i][j]);
                    }
        }
        __syncthreads();
    }
}

// ---------------------------------------------------------------------------
extern "C" void kernel_launch(void* const* d_in, const int* in_sizes, int n_in,
                              void* d_out, int out_size) {
    const float* x     = (const float*)d_in[0];
    const float* dw0w  = (const float*)d_in[1];
    const float* dw0b  = (const float*)d_in[2];
    const float* f0w1  = (const float*)d_in[3];
    const float* f0b1  = (const float*)d_in[4];
    const float* f0w2  = (const float*)d_in[5];
    const float* f0b2  = (const float*)d_in[6];
    const float* qkvw  = (const float*)d_in[7];
    const float* qkvb  = (const float*)d_in[8];
    const float* w7    = (const float*)d_in[9];
    const float* b7    = (const float*)d_in[10];
    const float* w5    = (const float*)d_in[11];
    const float* b5    = (const float*)d_in[12];
    const float* w3    = (const float*)d_in[13];
    const float* b3    = (const float*)d_in[14];
    const float* ab    = (const float*)d_in[15];
    const float* pw_   = (const float*)d_in[16];
    const float* pb    = (const float*)d_in[17];
    const float* dw1w  = (const float*)d_in[18];
    const float* dw1b  = (const float*)d_in[19];
    const float* f1w1  = (const float*)d_in[20];
    const float* f1b1  = (const float*)d_in[21];
    const float* f1w2  = (const float*)d_in[22];
    const float* f1b2  = (const float*)d_in[23];
    float* out = (float*)d_out;

    float *A, *C, *H;
    cudaGetSymbolAddress((void**)&A, g_A);
    cudaGetSymbolAddress((void**)&C, g_C);
    cudaGetSymbolAddress((void**)&H, g_H);

    cudaFuncSetAttribute(attn_kernel,
        cudaFuncAttributeMaxDynamicSharedMemorySize, ATT_SMEM_BYTES);

    // 1. A = x + dw0(x)                       (-> channel-major)
    dw3_res<1><<<XN/256, 256>>>(x, dw0w, dw0b, A);
    // 2. H = hswish(W1 @ A + b1)              M=1024 K=512
    tgemm<0><<<dim3(NTOT/64, 4), 256>>>(f0w1, A, f0b1, nullptr, H, 512, NTOT);
    // 3. A = A + (W2 @ H + b2)                M=512 K=1024
    tgemm<1><<<dim3(NTOT/64, 2), 256>>>(f0w2, H, f0b2, A, A, 1024, NTOT);
    // 4. attention -> C = hswish(concat)      [512][win*49]
    attn_kernel<<<1024, 256, ATT_SMEM_BYTES>>>(A, qkvw, qkvb, w7,b7, w5,b5, w3,b3, ab, C);
    // 5. A += merge(proj @ C + pb)            M=512 K=512
    tgemm<2><<<dim3(NTOT/64, 2), 256>>>(pw_, C, pb, A, A, 512, NTOT);
    // 6. C = A + dw1(A)
    dw3_res<0><<<XN/256, 256>>>(A, dw1w, dw1b, C);
    // 7. H = hswish(W1' @ C + b1')            M=1024 K=512
    tgemm<0><<<dim3(NTOT/64, 4), 256>>>(f1w1, C, f1b1, nullptr, H, 512, NTOT);
    // 8. out = C + (W2' @ H + b2')            M=512 K=1024, std layout out
    tgemm<3><<<dim3(NTOT/64, 2), 256>>>(f1w2, H, f1b2, C, out, 1024, NTOT);
}

// round 4
// speedup vs baseline: 1.7868x; 1.2212x over previous
#include <cuda_runtime.h>
#include <cstdint>

#define XN (64*512*28*28)      // 25,690,112  = 512 x 50176
#define HN (64*1024*28*28)     // 51,380,224  = 1024 x 50176
#define NTOT 50176

__device__ float g_A[XN];
__device__ float g_C[XN];
__device__ float g_H[HN];

__device__ __forceinline__ float hswish(float v){
    float r = v + 3.0f;
    r = fminf(fmaxf(r, 0.0f), 6.0f);
    return v * r * (1.0f/6.0f);
}

__device__ __forceinline__ float to_tf32(float x){
    uint32_t u;
    asm("cvt.rna.tf32.f32 %0, %1;" : "=r"(u) : "f"(x));
    return __uint_as_float(u);
}

__device__ __forceinline__ void mma_tf32(float* d, const uint32_t* a, const uint32_t* b){
    asm volatile("mma.sync.aligned.m16n8k8.row.col.f32.tf32.tf32.f32 "
        "{%0,%1,%2,%3}, {%4,%5,%6,%7}, {%8,%9}, {%0,%1,%2,%3};"
        : "+f"(d[0]), "+f"(d[1]), "+f"(d[2]), "+f"(d[3])
        : "r"(a[0]), "r"(a[1]), "r"(a[2]), "r"(a[3]), "r"(b[0]), "r"(b[1]));
}

// ---------------------------------------------------------------------------
// depthwise 3x3 + residual. Channel-major activations: plane p = c*64 + b.
// ---------------------------------------------------------------------------
template<int IN_STD>
__global__ __launch_bounds__(256) void dw3_res(const float* __restrict__ x,
        const float* __restrict__ w, const float* __restrict__ b,
        float* __restrict__ out){
    int idx = blockIdx.x*256 + threadIdx.x;
    int hw = idx % 784;
    int p  = idx / 784;               // p = c*64 + bimg
    int c  = p >> 6;
    int h  = hw/28, wc = hw%28;
    const float* xp;
    if(IN_STD){
        int bimg = p & 63;
        xp = x + ((size_t)bimg*512 + c)*784;
    } else {
        xp = x + (size_t)p*784;
    }
    const float* wp = w + c*9;
    float acc = b[c];
    #pragma unroll
    for(int dy=0;dy<3;dy++){
        int hh = h + dy - 1;
        if(hh<0||hh>=28) continue;
        #pragma unroll
        for(int dx=0;dx<3;dx++){
            int ww = wc + dx - 1;
            if(ww<0||ww>=28) continue;
            acc += wp[dy*3+dx]*xp[hh*28+ww];
        }
    }
    out[(size_t)p*784 + hw] = xp[hw] + acc;
}

// ---------------------------------------------------------------------------
// TF32 tensor GEMM, double-buffered.
// Block 256(M) x 128(N), BK=16, 256 thr = 8 warps (4m x 2n), warp tile 64x64.
// Out[m][n] = epi( sum_k W[m][k]*In[k][n] + bias[m] )
// MODE 0: hswish   MODE 1: +Res (same layout)
// MODE 2: proj (window-merge index) + Res   MODE 3: std [B][C][HW] + Res
// Requires M%256==0, Nn%128==0, K%16==0.
// ---------------------------------------------------------------------------
#define AS_P 264
#define BS_P 136
#define AS_ST (16*AS_P)          // floats per A stage
#define BS_ST (16*BS_P)
#define TG_SMEM ((2*AS_ST + 2*BS_ST)*4)   // 51,200 bytes

template<int MODE>
__global__ __launch_bounds__(256) void tgemm(
        const float* __restrict__ Wm, const float* __restrict__ In,
        const float* __restrict__ bias, const float* __restrict__ Res,
        float* __restrict__ Out, int K, int Nn)
{
    extern __shared__ float sm[];
    float* Asm = sm;                    // [2][16][AS_P]
    float* Bsm = sm + 2*AS_ST;          // [2][16][BS_P]

    const int tid  = threadIdx.x;
    const int lane = tid & 31, wid = tid >> 5;
    const int bn0  = blockIdx.x*128;
    const int bm0  = blockIdx.y*256;
    const int wm0  = (wid>>1)*64, wn0 = (wid&1)*64;
    const int r = lane>>2, c = lane&3;

    float acc[4][8][4];
    #pragma unroll
    for(int i=0;i<4;i++)
        #pragma unroll
        for(int j=0;j<8;j++)
            #pragma unroll
            for(int q=0;q<4;q++) acc[i][j][q]=0.f;

    const float* wrow = Wm + (size_t)(bm0 + tid)*K;
    const int bk = tid>>4, bc = (tid&15)*8;
    const float* bbase = In + (size_t)bk*Nn + bn0 + bc;

    float4 ra[4]; float4 rb0, rb1;
    const int nk = K>>4;

    // ---- prologue: tile 0 ----
    #pragma unroll
    for(int q=0;q<4;q++) ra[q] = *(const float4*)(wrow + q*4);
    rb0 = *(const float4*)(bbase);
    rb1 = *(const float4*)(bbase + 4);
    {
        float* As0 = Asm; float* Bs0 = Bsm;
        #pragma unroll
        for(int q=0;q<4;q++){
            As0[(q*4+0)*AS_P + tid] = to_tf32(ra[q].x);
            As0[(q*4+1)*AS_P + tid] = to_tf32(ra[q].y);
            As0[(q*4+2)*AS_P + tid] = to_tf32(ra[q].z);
            As0[(q*4+3)*AS_P + tid] = to_tf32(ra[q].w);
        }
        float4 t0, t1;
        t0.x=to_tf32(rb0.x); t0.y=to_tf32(rb0.y); t0.z=to_tf32(rb0.z); t0.w=to_tf32(rb0.w);
        t1.x=to_tf32(rb1.x); t1.y=to_tf32(rb1.y); t1.z=to_tf32(rb1.z); t1.w=to_tf32(rb1.w);
        *(float4*)&Bs0[bk*BS_P + bc]     = t0;
        *(float4*)&Bs0[bk*BS_P + bc + 4] = t1;
    }
    __syncthreads();

    for(int it=0; it<nk; ++it){
        // issue global loads for next tile
        if(it+1 < nk){
            int k0 = (it+1)<<4;
            #pragma unroll
            for(int q=0;q<4;q++) ra[q] = *(const float4*)(wrow + k0 + q*4);
            rb0 = *(const float4*)(bbase + (size_t)k0*Nn);
            rb1 = *(const float4*)(bbase + (size_t)k0*Nn + 4);
        }
        // compute on stage it&1
        {
            const float* As = Asm + (it&1)*AS_ST;
            const float* Bs = Bsm + (it&1)*BS_ST;
            #pragma unroll
            for(int kk=0; kk<16; kk+=8){
                uint32_t af[4][4], bf[8][2];
                #pragma unroll
                for(int mi=0;mi<4;mi++){
                    int m = wm0 + mi*16 + r;
                    af[mi][0] = __float_as_uint(As[(kk+c  )*AS_P + m  ]);
                    af[mi][1] = __float_as_uint(As[(kk+c  )*AS_P + m+8]);
                    af[mi][2] = __float_as_uint(As[(kk+c+4)*AS_P + m  ]);
                    af[mi][3] = __float_as_uint(As[(kk+c+4)*AS_P + m+8]);
                }
                #pragma unroll
                for(int ni=0;ni<8;ni++){
                    int n = wn0 + ni*8 + r;
                    bf[ni][0] = __float_as_uint(Bs[(kk+c  )*BS_P + n]);
                    bf[ni][1] = __float_as_uint(Bs[(kk+c+4)*BS_P + n]);
                }
                #pragma unroll
                for(int mi=0;mi<4;mi++)
                    #pragma unroll
                    for(int ni=0;ni<8;ni++)
                        mma_tf32(acc[mi][ni], af[mi], bf[ni]);
            }
        }
        // store next tile into other stage
        if(it+1 < nk){
            __syncthreads();
            float* As = Asm + ((it+1)&1)*AS_ST;
            float* Bs = Bsm + ((it+1)&1)*BS_ST;
            #pragma unroll
            for(int q=0;q<4;q++){
                As[(q*4+0)*AS_P + tid] = to_tf32(ra[q].x);
                As[(q*4+1)*AS_P + tid] = to_tf32(ra[q].y);
                As[(q*4+2)*AS_P + tid] = to_tf32(ra[q].z);
                As[(q*4+3)*AS_P + tid] = to_tf32(ra[q].w);
            }
            float4 t0, t1;
            t0.x=to_tf32(rb0.x); t0.y=to_tf32(rb0.y); t0.z=to_tf32(rb0.z); t0.w=to_tf32(rb0.w);
            t1.x=to_tf32(rb1.x); t1.y=to_tf32(rb1.y); t1.z=to_tf32(rb1.z); t1.w=to_tf32(rb1.w);
            *(float4*)&Bs[bk*BS_P + bc]     = t0;
            *(float4*)&Bs[bk*BS_P + bc + 4] = t1;
            __syncthreads();
        }
    }

    // ---- epilogue ----
    #pragma unroll
    for(int mi=0;mi<4;mi++){
        int mA = bm0 + wm0 + mi*16 + r;
        float bv0 = bias[mA], bv1 = bias[mA+8];
        #pragma unroll
        for(int ni=0;ni<8;ni++){
            int n = bn0 + wn0 + ni*8 + 2*c;
            #pragma unroll
            for(int half=0; half<2; half++){
                int m = mA + half*8;
                float bv = half? bv1:bv0;
                float v0 = acc[mi][ni][half*2+0] + bv;
                float v1 = acc[mi][ni][half*2+1] + bv;
                if(MODE==0){
                    size_t o = (size_t)m*Nn + n;
                    float2 w2; w2.x = hswish(v0); w2.y = hswish(v1);
                    *(float2*)(Out + o) = w2;
                } else if(MODE==1){
                    size_t o = (size_t)m*Nn + n;
                    float2 rv = *(const float2*)(Res + o);
                    float2 w2; w2.x = rv.x + v0; w2.y = rv.y + v1;
                    *(float2*)(Out + o) = w2;
                } else if(MODE==2){
                    #pragma unroll
                    for(int e=0;e<2;e++){
                        int nn = n+e; float v = e? v1:v0;
                        int win = nn/49, t = nn - win*49;
                        int bimg = win>>4, wi=(win>>2)&3, wj=win&3;
                        int rr = t/7, cc = t - rr*7;
                        size_t idx = ((size_t)m*64 + bimg)*784 + (wi*7+rr)*28 + wj*7+cc;
                        Out[idx] = Res[idx] + v;
                    }
                } else {
                    size_t ri = (size_t)m*Nn + n;
                    #pragma unroll
                    for(int e=0;e<2;e++){
                        int nn = n+e; float v = e? v1:v0;
                        int bimg = nn/784, hw = nn - bimg*784;
                        Out[(size_t)bimg*401408 + (size_t)m*784 + hw] = Res[ri+e] + v;
                    }
                }
            }
        }
    }
}

// ---------------------------------------------------------------------------
// Cascaded window attention (unchanged from R2).
// ---------------------------------------------------------------------------
#define AP 52
#define SP_F   (64*AP)
#define Y_F    (80*AP)
#define QC_F   (49*20)
#define KT_F   (49*20)
#define ATT_F  (49*AP)
#define QW_F   (96*64)
#define ATT_SMEM_FLOATS (SP_F + Y_F + QC_F + KT_F + ATT_F + QW_F + 96)
#define ATT_SMEM_BYTES  (ATT_SMEM_FLOATS*4)

__global__ __launch_bounds__(256) void attn_kernel(
    const float* __restrict__ A,
    const float* __restrict__ qkvw, const float* __restrict__ qkvb,
    const float* __restrict__ w7, const float* __restrict__ b7,
    const float* __restrict__ w5, const float* __restrict__ b5,
    const float* __restrict__ w3, const float* __restrict__ b3,
    const float* __restrict__ abias,
    float* __restrict__ C)
{
    extern __shared__ float sm[];
    float* sp  = sm;                 // [64][AP]
    float* y   = sp  + SP_F;         // [80][AP]
    float* qc2 = y   + Y_F;          // [49][20]
    float* kt  = qc2 + QC_F;         // [49][20]
    float* att = kt  + KT_F;         // [49][AP]
    float* qw  = att + ATT_F;        // [96][64]
    float* qb  = qw  + QW_F;         // [96]

    const int w = blockIdx.x, tid = threadIdx.x;
    const int bimg = w>>4, wi=(w>>2)&3, wj=w&3;
    const int off0 = (wi*7)*28 + wj*7;

    for(int hd=0; hd<8; hd++){
        for(int i=tid;i<96*64;i+=256) qw[i] = qkvw[hd*96*64 + i];
        if(tid<96) qb[tid] = qkvb[hd*96 + tid];
        for(int i=tid;i<64*49;i+=256){
            int cch = i/49, t = i - cch*49;
            int r = t/7, cc = t - r*7;
            float v = A[((size_t)(hd*64+cch)*64 + bimg)*784 + off0 + r*28 + cc];
            if(hd==0) sp[cch*AP+t] = v; else sp[cch*AP+t] += v;
        }
        __syncthreads();

        for(int u=tid; u<24*13; u+=256){
            int o0 = (u/13)*4, t0 = (u%13)*4;
            float acc[4][4];
            #pragma unroll
            for(int i=0;i<4;i++){ float bb=qb[o0+i];
                #pragma unroll
                for(int j=0;j<4;j++) acc[i][j]=bb; }
            for(int cI=0;cI<64;cI+=4){
                float4 s0=*(const float4*)&sp[(cI+0)*AP+t0];
                float4 s1=*(const float4*)&sp[(cI+1)*AP+t0];
                float4 s2=*(const float4*)&sp[(cI+2)*AP+t0];
                float4 s3=*(const float4*)&sp[(cI+3)*AP+t0];
                #pragma unroll
                for(int i=0;i<4;i++){
                    float4 qv = *(const float4*)&qw[(o0+i)*64+cI];
                    acc[i][0] += qv.x*s0.x + qv.y*s1.x + qv.z*s2.x + qv.w*s3.x;
                    acc[i][1] += qv.x*s0.y + qv.y*s1.y + qv.z*s2.y + qv.w*s3.y;
                    acc[i][2] += qv.x*s0.z + qv.y*s1.z + qv.z*s2.z + qv.w*s3.z;
                    acc[i][3] += qv.x*s0.w + qv.y*s1.w + qv.z*s2.w + qv.w*s3.w;
                }
            }
            #pragma unroll
            for(int i=0;i<4;i++)
                #pragma unroll
                for(int j=0;j<4;j++){
                    int o = o0+i, t = t0+j;
                    if(t<49){
                        float v = acc[i][j];
                        if(o<16)      y[o*AP+t] = v;
                        else if(o<32) kt[t*20 + (o-16)] = v;
                        else          y[(o-16)*AP+t] = v;
                    }
                }
        }
        __syncthreads();

        {
            int ks = (hd==0)?7:((hd==1)?5:3);
            int pad = ks>>1;
            const float* cw; const float* cb;
            if(hd==0){ cw=w7; cb=b7; }
            else if(hd==1){ cw=w5; cb=b5; }
            else { cw = w3 + (hd-2)*16*9; cb = b3 + (hd-2)*16; }
            for(int i=tid;i<16*49;i+=256){
                int ch=i/49, t=i-ch*49; int r=t/7, cc=t-r*7;
                float acc = cb[ch];
                const float* wp = cw + ch*ks*ks;
                for(int dy=0;dy<ks;dy++){
                    int rr = r+dy-pad; if(rr<0||rr>=7) continue;
                    for(int dx=0;dx<ks;dx++){
                        int c2 = cc+dx-pad; if(c2<0||c2>=7) continue;
                        acc += wp[dy*ks+dx]*y[ch*AP + rr*7+c2];
                    }
                }
                qc2[t*20+ch]=acc;
            }
        }
        __syncthreads();

        for(int i=tid;i<49*49;i+=256){
            int n=i/49, m=i-n*49;
            float acc=0.f;
            #pragma unroll
            for(int cI=0;cI<16;cI+=4){
                float4 qv=*(const float4*)&qc2[n*20+cI];
                float4 kv=*(const float4*)&kt[m*20+cI];
                acc += qv.x*kv.x+qv.y*kv.y+qv.z*kv.z+qv.w*kv.w;
            }
            int r1=n/7, c1=n-(n/7)*7, r2=m/7, c2=m-(m/7)*7;
            int dr=r1-r2; if(dr<0)dr=-dr;
            int dc=c1-c2; if(dc<0)dc=-dc;
            att[n*AP+m] = acc*0.25f + abias[hd*49 + dr*7+dc];
        }
        __syncthreads();

        if(tid<49){
            float mx=-1e30f;
            for(int m=0;m<49;m++) mx = fmaxf(mx, att[tid*AP+m]);
            float s=0.f;
            for(int m=0;m<49;m++){ float e=__expf(att[tid*AP+m]-mx); att[tid*AP+m]=e; s+=e; }
            float inv = 1.f/s;
            for(int m=0;m<49;m++) att[tid*AP+m]*=inv;
        }
        __syncthreads();

        float* Cw = C + (size_t)(hd*64)*NTOT + w*49;
        for(int u=tid; u<16*13; u+=256){
            int d0=(u/13)*4, t0=(u%13)*4;
            float acc[4][4];
            #pragma unroll
            for(int i=0;i<4;i++)
                #pragma unroll
                for(int j=0;j<4;j++) acc[i][j]=0.f;
            for(int m=0;m<48;m+=4){
                float4 a0=*(const float4*)&att[(t0+0)*AP+m];
                float4 a1=*(const float4*)&att[(t0+1)*AP+m];
                float4 a2=*(const float4*)&att[(t0+2)*AP+m];
                float4 a3=*(const float4*)&att[(t0+3)*AP+m];
                #pragma unroll
                for(int i=0;i<4;i++){
                    float4 vv = *(const float4*)&y[(16+d0+i)*AP+m];
                    acc[i][0]+=vv.x*a0.x+vv.y*a0.y+vv.z*a0.z+vv.w*a0.w;
                    acc[i][1]+=vv.x*a1.x+vv.y*a1.y+vv.z*a1.z+vv.w*a1.w;
                    acc[i][2]+=vv.x*a2.x+vv.y*a2.y+vv.z*a2.z+vv.w*a2.w;
                    acc[i][3]+=vv.x*a3.x+vv.y*a3.y+vv.z*a3.z+vv.w*a3.w;
                }
            }
            {
                int m=48;
                #pragma unroll
                for(int i=0;i<4;i++){
                    float vv = y[(16+d0+i)*AP+m];
                    acc[i][0]+=vv*att[(t0+0)*AP+m];
                    acc[i][1]+=vv*att[(t0+1)*AP+m];
                    acc[i][2]+=vv*att[(t0+2)*AP+m];
                    acc[i][3]+=vv*att[(t0+3)*AP+m];
                }
            }
            #pragma unroll
            for(int i=0;i<4;i++)
                #pragma unroll
                for(int j=0;j<4;j++)
                    if(t0+j<49){
                        sp[(d0+i)*AP + t0+j] = acc[i][j];
                        Cw[(size_t)(d0+i)*NTOT + t0+j] = hswish(acc[i][j]);
                    }
        }
        __syncthreads();
    }
}

// ---------------------------------------------------------------------------
extern "C" void kernel_launch(void* const* d_in, const int* in_sizes, int n_in,
                              void* d_out, int out_size) {
    const float* x     = (const float*)d_in[0];
    const float* dw0w  = (const float*)d_in[1];
    const float* dw0b  = (const float*)d_in[2];
    const float* f0w1  = (const float*)d_in[3];
    const float* f0b1  = (const float*)d_in[4];
    const float* f0w2  = (const float*)d_in[5];
    const float* f0b2  = (const float*)d_in[6];
    const float* qkvw  = (const float*)d_in[7];
    const float* qkvb  = (const float*)d_in[8];
    const float* w7    = (const float*)d_in[9];
    const float* b7    = (const float*)d_in[10];
    const float* w5    = (const float*)d_in[11];
    const float* b5    = (const float*)d_in[12];
    const float* w3    = (const float*)d_in[13];
    const float* b3    = (const float*)d_in[14];
    const float* ab    = (const float*)d_in[15];
    const float* pw_   = (const float*)d_in[16];
    const float* pb    = (const float*)d_in[17];
    const float* dw1w  = (const float*)d_in[18];
    const float* dw1b  = (const float*)d_in[19];
    const float* f1w1  = (const float*)d_in[20];
    const float* f1b1  = (const float*)d_in[21];
    const float* f1w2  = (const float*)d_in[22];
    const float* f1b2  = (const float*)d_in[23];
    float* out = (float*)d_out;

    float *A, *C, *H;
    cudaGetSymbolAddress((void**)&A, g_A);
    cudaGetSymbolAddress((void**)&C, g_C);
    cudaGetSymbolAddress((void**)&H, g_H);

    cudaFuncSetAttribute(attn_kernel,
        cudaFuncAttributeMaxDynamicSharedMemorySize, ATT_SMEM_BYTES);
    cudaFuncSetAttribute(tgemm<0>, cudaFuncAttributeMaxDynamicSharedMemorySize, TG_SMEM);
    cudaFuncSetAttribute(tgemm<1>, cudaFuncAttributeMaxDynamicSharedMemorySize, TG_SMEM);
    cudaFuncSetAttribute(tgemm<2>, cudaFuncAttributeMaxDynamicSharedMemorySize, TG_SMEM);
    cudaFuncSetAttribute(tgemm<3>, cudaFuncAttributeMaxDynamicSharedMemorySize, TG_SMEM);

    // 1. A = x + dw0(x)
    dw3_res<1><<<XN/256, 256>>>(x, dw0w, dw0b, A);
    // 2. H = hswish(W1 @ A + b1)              M=1024 K=512
    tgemm<0><<<dim3(NTOT/128, 4), 256, TG_SMEM>>>(f0w1, A, f0b1, nullptr, H, 512, NTOT);
    // 3. A = A + (W2 @ H + b2)                M=512 K=1024
    tgemm<1><<<dim3(NTOT/128, 2), 256, TG_SMEM>>>(f0w2, H, f0b2, A, A, 1024, NTOT);
    // 4. attention -> C = hswish(concat)      [512][win*49]
    attn_kernel<<<1024, 256, ATT_SMEM_BYTES>>>(A, qkvw, qkvb, w7,b7, w5,b5, w3,b3, ab, C);
    // 5. A += merge(proj @ C + pb)            M=512 K=512
    tgemm<2><<<dim3(NTOT/128, 2), 256, TG_SMEM>>>(pw_, C, pb, A, A, 512, NTOT);
    // 6. C = A + dw1(A)
    dw3_res<0><<<XN/256, 256>>>(A, dw1w, dw1b, C);
    // 7. H = hswish(W1' @ C + b1')            M=1024 K=512
    tgemm<0><<<dim3(NTOT/128, 4), 256, TG_SMEM>>>(f1w1, C, f1b1, nullptr, H, 512, NTOT);
    // 8. out = C + (W2' @ H + b2')            M=512 K=1024, std layout
    tgemm<3><<<dim3(NTOT/128, 2), 256, TG_SMEM>>>(f1w2, H, f1b2, C, out, 1024, NTOT);
}

// round 10
// speedup vs baseline: 2.0243x; 1.1329x over previous
#include <cuda_runtime.h>
#include <cuda_fp16.h>
#include <cstdint>

#define XN (64*512*28*28)      // 512 x 50176
#define HN (64*1024*28*28)     // 1024 x 50176
#define NTOT 50176

__device__ float g_A[XN];
__device__ float g_C[XN];
__device__ float g_H[HN];

__device__ __forceinline__ float hswish(float v){
    float r = v + 3.0f;
    r = fminf(fmaxf(r, 0.0f), 6.0f);
    return v * r * (1.0f/6.0f);
}
__device__ __forceinline__ uint32_t packh(float x, float y){
    __half2 h = __floats2half2_rn(x, y);
    return *(uint32_t*)&h;
}
__device__ __forceinline__ void mma_f16(float* d, const uint32_t* a, const uint32_t* b){
    asm volatile("mma.sync.aligned.m16n8k16.row.col.f32.f16.f16.f32 "
        "{%0,%1,%2,%3}, {%4,%5,%6,%7}, {%8,%9}, {%0,%1,%2,%3};"
        : "+f"(d[0]), "+f"(d[1]), "+f"(d[2]), "+f"(d[3])
        : "r"(a[0]), "r"(a[1]), "r"(a[2]), "r"(a[3]), "r"(b[0]), "r"(b[1]));
}

// ---------------------------------------------------------------------------
// depthwise 3x3 + residual (channel-major activations, plane p = c*64 + b)
// ---------------------------------------------------------------------------
template<int IN_STD>
__global__ __launch_bounds__(256) void dw3_res(const float* __restrict__ x,
        const float* __restrict__ w, const float* __restrict__ b,
        float* __restrict__ out){
    int idx = blockIdx.x*256 + threadIdx.x;
    int hw = idx % 784;
    int p  = idx / 784;
    int c  = p >> 6;
    int h  = hw/28, wc = hw%28;
    const float* xp;
    if(IN_STD){
        int bimg = p & 63;
        xp = x + ((size_t)bimg*512 + c)*784;
    } else {
        xp = x + (size_t)p*784;
    }
    const float* wp = w + c*9;
    float acc = b[c];
    #pragma unroll
    for(int dy=0;dy<3;dy++){
        int hh = h + dy - 1;
        if(hh<0||hh>=28) continue;
        #pragma unroll
        for(int dx=0;dx<3;dx++){
            int ww = wc + dx - 1;
            if(ww<0||ww>=28) continue;
            acc += wp[dy*3+dx]*xp[hh*28+ww];
        }
    }
    out[(size_t)p*784 + hw] = xp[hw] + acc;
}

// ---------------------------------------------------------------------------
// fp16 tensor GEMM (fp32 accum). Out[m][n] = epi( sum_k W[m][k]*In[k][n] + b[m] )
// Block 256(M) x 128(N), BK=16, 256 thr = 8 warps (4m x 2n), warp 64x64.
// A smem [m][kpair] pitch 12 u32; B smem [n][kpair] pitch 12 u32 (transposed).
// Double-buffered with register staging.
// MODE 0 hswish | 1 +Res | 2 proj window-merge +Res | 3 std layout +Res
// ---------------------------------------------------------------------------
#define HP 12                       // uint32 pitch per row (8 used)
#define A_ST (128*HP)
#define B_ST (128*HP)

template<int MODE>
__global__ __launch_bounds__(256) void hgemm(
        const float* __restrict__ Wm, const float* __restrict__ In,
        const float* __restrict__ bias, const float* __restrict__ Res,
        float* __restrict__ Out, int K, int Nn)
{
    __shared__ uint32_t As[2][A_ST];    // A[m=0..255 -> 2x128? no: 256 rows] -- see below
    __shared__ uint32_t As2[2][A_ST];   // rows 128..255
    __shared__ uint32_t Bs[2][B_ST];

    const int tid  = threadIdx.x;
    const int lane = tid & 31, wid = tid >> 5;
    const int bn0  = blockIdx.x*128;
    const int bm0  = blockIdx.y*256;
    const int wm0  = (wid>>1)*64, wn0 = (wid&1)*64;
    const int r = lane>>2, c = lane&3;

    float acc[4][8][4];
    #pragma unroll
    for(int i=0;i<4;i++)
        #pragma unroll
        for(int j=0;j<8;j++)
            #pragma unroll
            for(int q=0;q<4;q++) acc[i][j][q]=0.f;

    // A mapping: thread t handles m = t (one row of 256), 16 k (4 float4? no)
    // 256 rows x 16 k = 4096 floats / 256 thr = 16 floats: m=t, all 16 k.
    const float* wrow = Wm + (size_t)(bm0 + tid)*K;
    // B mapping: kp = t&7 (k-pair), n0 = (t>>3)*4
    const int kp = tid & 7, bn4 = (tid>>3)*4;
    const float* bbase = In + (size_t)(2*kp)*Nn + bn0 + bn4;

    float4 ra[4]; float4 rb0, rb1;
    const int nk = K>>4;

    // helper lambda-ish macros via code duplication
    // ---- prologue: load + store chunk 0 ----
    #pragma unroll
    for(int q=0;q<4;q++) ra[q] = *(const float4*)(wrow + q*4);
    rb0 = *(const float4*)(bbase);
    rb1 = *(const float4*)(bbase + Nn);
    {
        uint32_t* Ad = (tid<128)? &As[0][tid*HP] : &As2[0][(tid-128)*HP];
        Ad[0]=packh(ra[0].x,ra[0].y); Ad[1]=packh(ra[0].z,ra[0].w);
        Ad[2]=packh(ra[1].x,ra[1].y); Ad[3]=packh(ra[1].z,ra[1].w);
        Ad[4]=packh(ra[2].x,ra[2].y); Ad[5]=packh(ra[2].z,ra[2].w);
        Ad[6]=packh(ra[3].x,ra[3].y); Ad[7]=packh(ra[3].z,ra[3].w);
        Bs[0][(bn4+0)*HP+kp]=packh(rb0.x,rb1.x);
        Bs[0][(bn4+1)*HP+kp]=packh(rb0.y,rb1.y);
        Bs[0][(bn4+2)*HP+kp]=packh(rb0.z,rb1.z);
        Bs[0][(bn4+3)*HP+kp]=packh(rb0.w,rb1.w);
    }
    __syncthreads();

    for(int it=0; it<nk; ++it){
        const int cur = it&1;
        if(it+1 < nk){
            int k0 = (it+1)<<4;
            #pragma unroll
            for(int q=0;q<4;q++) ra[q] = *(const float4*)(wrow + k0 + q*4);
            rb0 = *(const float4*)(bbase + (size_t)k0*Nn);
            rb1 = *(const float4*)(bbase + (size_t)(k0+1)*Nn);
        }
        // compute on stage cur
        {
            const uint32_t* Au = (wid>>1 < 2)? As[cur] : As2[cur];
            const int wml = (wid>>1 < 2)? wm0 : wm0-128;
            uint32_t af[4][4], bf[8][2];
            #pragma unroll
            for(int mi=0;mi<4;mi++){
                int m = wml + mi*16 + r;
                af[mi][0] = Au[m*HP + c];
                af[mi][1] = Au[(m+8)*HP + c];
                af[mi][2] = Au[m*HP + c+4];
                af[mi][3] = Au[(m+8)*HP + c+4];
            }
            #pragma unroll
            for(int ni=0;ni<8;ni++){
                int n = wn0 + ni*8 + r;
                bf[ni][0] = Bs[cur][n*HP + c];
                bf[ni][1] = Bs[cur][n*HP + c+4];
            }
            #pragma unroll
            for(int mi=0;mi<4;mi++)
                #pragma unroll
                for(int ni=0;ni<8;ni++)
                    mma_f16(acc[mi][ni], af[mi], bf[ni]);
        }
        if(it+1 < nk){
            const int nxt = (it+1)&1;
            __syncthreads();
            uint32_t* Ad = (tid<128)? &As[nxt][tid*HP] : &As2[nxt][(tid-128)*HP];
            Ad[0]=packh(ra[0].x,ra[0].y); Ad[1]=packh(ra[0].z,ra[0].w);
            Ad[2]=packh(ra[1].x,ra[1].y); Ad[3]=packh(ra[1].z,ra[1].w);
            Ad[4]=packh(ra[2].x,ra[2].y); Ad[5]=packh(ra[2].z,ra[2].w);
            Ad[6]=packh(ra[3].x,ra[3].y); Ad[7]=packh(ra[3].z,ra[3].w);
            Bs[nxt][(bn4+0)*HP+kp]=packh(rb0.x,rb1.x);
            Bs[nxt][(bn4+1)*HP+kp]=packh(rb0.y,rb1.y);
            Bs[nxt][(bn4+2)*HP+kp]=packh(rb0.z,rb1.z);
            Bs[nxt][(bn4+3)*HP+kp]=packh(rb0.w,rb1.w);
            __syncthreads();
        }
    }

    // ---- epilogue (D layout of m16n8: d0,d1 row r cols 2c,2c+1; d2,d3 row r+8) ----
    #pragma unroll
    for(int mi=0;mi<4;mi++){
        int mA = bm0 + wm0 + mi*16 + r;
        float bv0 = bias[mA], bv1 = bias[mA+8];
        #pragma unroll
        for(int ni=0;ni<8;ni++){
            int n = bn0 + wn0 + ni*8 + 2*c;
            #pragma unroll
            for(int half=0; half<2; half++){
                int m = mA + half*8;
                float bv = half? bv1:bv0;
                float v0 = acc[mi][ni][half*2+0] + bv;
                float v1 = acc[mi][ni][half*2+1] + bv;
                if(MODE==0){
                    size_t o = (size_t)m*Nn + n;
                    float2 w2; w2.x = hswish(v0); w2.y = hswish(v1);
                    *(float2*)(Out + o) = w2;
                } else if(MODE==1){
                    size_t o = (size_t)m*Nn + n;
                    float2 rv = *(const float2*)(Res + o);
                    float2 w2; w2.x = rv.x + v0; w2.y = rv.y + v1;
                    *(float2*)(Out + o) = w2;
                } else if(MODE==2){
                    #pragma unroll
                    for(int e=0;e<2;e++){
                        int nn = n+e; float v = e? v1:v0;
                        int win = nn/49, t = nn - win*49;
                        int bimg = win>>4, wi=(win>>2)&3, wj=win&3;
                        int r2 = t/7, c2 = t - r2*7;
                        size_t idx = ((size_t)m*64 + bimg)*784 + (wi*7+r2)*28 + wj*7+c2;
                        Out[idx] = Res[idx] + v;
                    }
                } else {
                    size_t ri = (size_t)m*Nn + n;
                    #pragma unroll
                    for(int e=0;e<2;e++){
                        int nn = n+e; float v = e? v1:v0;
                        int bimg = nn/784, hw = nn - bimg*784;
                        Out[(size_t)bimg*401408 + (size_t)m*784 + hw] = Res[ri+e] + v;
                    }
                }
            }
        }
    }
}

// ---------------------------------------------------------------------------
// Cascaded window attention (unchanged from R4).
// ---------------------------------------------------------------------------
#define AP 52
#define SP_F   (64*AP)
#define Y_F    (80*AP)
#define QC_F   (49*20)
#define KT_F   (49*20)
#define ATT_F  (49*AP)
#define QW_F   (96*64)
#define ATT_SMEM_FLOATS (SP_F + Y_F + QC_F + KT_F + ATT_F + QW_F + 96)
#define ATT_SMEM_BYTES  (ATT_SMEM_FLOATS*4)

__global__ __launch_bounds__(256) void attn_kernel(
    const float* __restrict__ A,
    const float* __restrict__ qkvw, const float* __restrict__ qkvb,
    const float* __restrict__ w7, const float* __restrict__ b7,
    const float* __restrict__ w5, const float* __restrict__ b5,
    const float* __restrict__ w3, const float* __restrict__ b3,
    const float* __restrict__ abias,
    float* __restrict__ C)
{
    extern __shared__ float sm[];
    float* sp  = sm;
    float* y   = sp  + SP_F;
    float* qc2 = y   + Y_F;
    float* kt  = qc2 + QC_F;
    float* att = kt  + KT_F;
    float* qw  = att + ATT_F;
    float* qb  = qw  + QW_F;

    const int w = blockIdx.x, tid = threadIdx.x;
    const int bimg = w>>4, wi=(w>>2)&3, wj=w&3;
    const int off0 = (wi*7)*28 + wj*7;

    for(int hd=0; hd<8; hd++){
        for(int i=tid;i<96*64;i+=256) qw[i] = qkvw[hd*96*64 + i];
        if(tid<96) qb[tid] = qkvb[hd*96 + tid];
        for(int i=tid;i<64*49;i+=256){
            int cch = i/49, t = i - cch*49;
            int r = t/7, cc = t - r*7;
            float v = A[((size_t)(hd*64+cch)*64 + bimg)*784 + off0 + r*28 + cc];
            if(hd==0) sp[cch*AP+t] = v; else sp[cch*AP+t] += v;
        }
        __syncthreads();

        for(int u=tid; u<24*13; u+=256){
            int o0 = (u/13)*4, t0 = (u%13)*4;
            float acc[4][4];
            #pragma unroll
            for(int i=0;i<4;i++){ float bb=qb[o0+i];
                #pragma unroll
                for(int j=0;j<4;j++) acc[i][j]=bb; }
            for(int cI=0;cI<64;cI+=4){
                float4 s0=*(const float4*)&sp[(cI+0)*AP+t0];
                float4 s1=*(const float4*)&sp[(cI+1)*AP+t0];
                float4 s2=*(const float4*)&sp[(cI+2)*AP+t0];
                float4 s3=*(const float4*)&sp[(cI+3)*AP+t0];
                #pragma unroll
                for(int i=0;i<4;i++){
                    float4 qv = *(const float4*)&qw[(o0+i)*64+cI];
                    acc[i][0] += qv.x*s0.x + qv.y*s1.x + qv.z*s2.x + qv.w*s3.x;
                    acc[i][1] += qv.x*s0.y + qv.y*s1.y + qv.z*s2.y + qv.w*s3.y;
                    acc[i][2] += qv.x*s0.z + qv.y*s1.z + qv.z*s2.z + qv.w*s3.z;
                    acc[i][3] += qv.x*s0.w + qv.y*s1.w + qv.z*s2.w + qv.w*s3.w;
                }
            }
            #pragma unroll
            for(int i=0;i<4;i++)
                #pragma unroll
                for(int j=0;j<4;j++){
                    int o = o0+i, t = t0+j;
                    if(t<49){
                        float v = acc[i][j];
                        if(o<16)      y[o*AP+t] = v;
                        else if(o<32) kt[t*20 + (o-16)] = v;
                        else          y[(o-16)*AP+t] = v;
                    }
                }
        }
        __syncthreads();

        {
            int ks = (hd==0)?7:((hd==1)?5:3);
            int pad = ks>>1;
            const float* cw; const float* cb;
            if(hd==0){ cw=w7; cb=b7; }
            else if(hd==1){ cw=w5; cb=b5; }
            else { cw = w3 + (hd-2)*16*9; cb = b3 + (hd-2)*16; }
            for(int i=tid;i<16*49;i+=256){
                int ch=i/49, t=i-ch*49; int r=t/7, cc=t-r*7;
                float acc = cb[ch];
                const float* wp = cw + ch*ks*ks;
                for(int dy=0;dy<ks;dy++){
                    int rr = r+dy-pad; if(rr<0||rr>=7) continue;
                    for(int dx=0;dx<ks;dx++){
                        int c2 = cc+dx-pad; if(c2<0||c2>=7) continue;
                        acc += wp[dy*ks+dx]*y[ch*AP + rr*7+c2];
                    }
                }
                qc2[t*20+ch]=acc;
            }
        }
        __syncthreads();

        for(int i=tid;i<49*49;i+=256){
            int n=i/49, m=i-n*49;
            float acc=0.f;
            #pragma unroll
            for(int cI=0;cI<16;cI+=4){
                float4 qv=*(const float4*)&qc2[n*20+cI];
                float4 kv=*(const float4*)&kt[m*20+cI];
                acc += qv.x*kv.x+qv.y*kv.y+qv.z*kv.z+qv.w*kv.w;
            }
            int r1=n/7, c1=n-(n/7)*7, r2=m/7, c2=m-(m/7)*7;
            int dr=r1-r2; if(dr<0)dr=-dr;
            int dc=c1-c2; if(dc<0)dc=-dc;
            att[n*AP+m] = acc*0.25f + abias[hd*49 + dr*7+dc];
        }
        __syncthreads();

        if(tid<49){
            float mx=-1e30f;
            for(int m=0;m<49;m++) mx = fmaxf(mx, att[tid*AP+m]);
            float s=0.f;
            for(int m=0;m<49;m++){ float e=__expf(att[tid*AP+m]-mx); att[tid*AP+m]=e; s+=e; }
            float inv = 1.f/s;
            for(int m=0;m<49;m++) att[tid*AP+m]*=inv;
        }
        __syncthreads();

        float* Cw = C + (size_t)(hd*64)*NTOT + w*49;
        for(int u=tid; u<16*13; u+=256){
            int d0=(u/13)*4, t0=(u%13)*4;
            float acc[4][4];
            #pragma unroll
            for(int i=0;i<4;i++)
                #pragma unroll
                for(int j=0;j<4;j++) acc[i][j]=0.f;
            for(int m=0;m<48;m+=4){
                float4 a0=*(const float4*)&att[(t0+0)*AP+m];
                float4 a1=*(const float4*)&att[(t0+1)*AP+m];
                float4 a2=*(const float4*)&att[(t0+2)*AP+m];
                float4 a3=*(const float4*)&att[(t0+3)*AP+m];
                #pragma unroll
                for(int i=0;i<4;i++){
                    float4 vv = *(const float4*)&y[(16+d0+i)*AP+m];
                    acc[i][0]+=vv.x*a0.x+vv.y*a0.y+vv.z*a0.z+vv.w*a0.w;
                    acc[i][1]+=vv.x*a1.x+vv.y*a1.y+vv.z*a1.z+vv.w*a1.w;
                    acc[i][2]+=vv.x*a2.x+vv.y*a2.y+vv.z*a2.z+vv.w*a2.w;
                    acc[i][3]+=vv.x*a3.x+vv.y*a3.y+vv.z*a3.z+vv.w*a3.w;
                }
            }
            {
                int m=48;
                #pragma unroll
                for(int i=0;i<4;i++){
                    float vv = y[(16+d0+i)*AP+m];
                    acc[i][0]+=vv*att[(t0+0)*AP+m];
                    acc[i][1]+=vv*att[(t0+1)*AP+m];
                    acc[i][2]+=vv*att[(t0+2)*AP+m];
                    acc[i][3]+=vv*att[(t0+3)*AP+m];
                }
            }
            #pragma unroll
            for(int i=0;i<4;i++)
                #pragma unroll
                for(int j=0;j<4;j++)
                    if(t0+j<49){
                        sp[(d0+i)*AP + t0+j] = acc[i][j];
                        Cw[(size_t)(d0+i)*NTOT + t0+j] = hswish(acc[i][j]);
                    }
        }
        __syncthreads();
    }
}

// ---------------------------------------------------------------------------
extern "C" void kernel_launch(void* const* d_in, const int* in_sizes, int n_in,
                              void* d_out, int out_size) {
    const float* x     = (const float*)d_in[0];
    const float* dw0w  = (const float*)d_in[1];
    const float* dw0b  = (const float*)d_in[2];
    const float* f0w1  = (const float*)d_in[3];
    const float* f0b1  = (const float*)d_in[4];
    const float* f0w2  = (const float*)d_in[5];
    const float* f0b2  = (const float*)d_in[6];
    const float* qkvw  = (const float*)d_in[7];
    const float* qkvb  = (const float*)d_in[8];
    const float* w7    = (const float*)d_in[9];
    const float* b7    = (const float*)d_in[10];
    const float* w5    = (const float*)d_in[11];
    const float* b5    = (const float*)d_in[12];
    const float* w3    = (const float*)d_in[13];
    const float* b3    = (const float*)d_in[14];
    const float* ab    = (const float*)d_in[15];
    const float* pw_   = (const float*)d_in[16];
    const float* pb    = (const float*)d_in[17];
    const float* dw1w  = (const float*)d_in[18];
    const float* dw1b  = (const float*)d_in[19];
    const float* f1w1  = (const float*)d_in[20];
    const float* f1b1  = (const float*)d_in[21];
    const float* f1w2  = (const float*)d_in[22];
    const float* f1b2  = (const float*)d_in[23];
    float* out = (float*)d_out;

    float *A, *C, *H;
    cudaGetSymbolAddress((void**)&A, g_A);
    cudaGetSymbolAddress((void**)&C, g_C);
    cudaGetSymbolAddress((void**)&H, g_H);

    cudaFuncSetAttribute(attn_kernel,
        cudaFuncAttributeMaxDynamicSharedMemorySize, ATT_SMEM_BYTES);

    // 1. A = x + dw0(x)
    dw3_res<1><<<XN/256, 256>>>(x, dw0w, dw0b, A);
    // 2. H = hswish(W1 @ A + b1)              M=1024 K=512
    hgemm<0><<<dim3(NTOT/128, 4), 256>>>(f0w1, A, f0b1, nullptr, H, 512, NTOT);
    // 3. A = A + (W2 @ H + b2)                M=512 K=1024
    hgemm<1><<<dim3(NTOT/128, 2), 256>>>(f0w2, H, f0b2, A, A, 1024, NTOT);
    // 4. attention -> C = hswish(concat)
    attn_kernel<<<1024, 256, ATT_SMEM_BYTES>>>(A, qkvw, qkvb, w7,b7, w5,b5, w3,b3, ab, C);
    // 5. A += merge(proj @ C + pb)            M=512 K=512
    hgemm<2><<<dim3(NTOT/128, 2), 256>>>(pw_, C, pb, A, A, 512, NTOT);
    // 6. C = A + dw1(A)
    dw3_res<0><<<XN/256, 256>>>(A, dw1w, dw1b, C);
    // 7. H = hswish(W1' @ C + b1')            M=1024 K=512
    hgemm<0><<<dim3(NTOT/128, 4), 256>>>(f1w1, C, f1b1, nullptr, H, 512, NTOT);
    // 8. out = C + (W2' @ H + b2')            M=512 K=1024, std layout
    hgemm<3><<<dim3(NTOT/128, 2), 256>>>(f1w2, H, f1b2, C, out, 1024, NTOT);
}

// round 11
// speedup vs baseline: 3.5488x; 1.7531x over previous
#include <cuda_runtime.h>
#include <cuda_fp16.h>
#include <cstdint>

#define XN (64*512*28*28)      // 512 x 50176
#define HN (64*1024*28*28)     // 1024 x 50176
#define NTOT 50176

__device__ float  g_A[XN];
__device__ float  g_C[XN];
__device__ __half g_A16[XN];
__device__ __half g_C16[XN];
__device__ __half g_H16[HN];
__device__ __half g_W16[2359296];   // f0w1|f0w2|pw|f1w1|f1w2

__device__ __forceinline__ float hswish(float v){
    float r = v + 3.0f;
    r = fminf(fmaxf(r, 0.0f), 6.0f);
    return v * r * (1.0f/6.0f);
}
__device__ __forceinline__ uint32_t smem_u32(const void* p){
    uint32_t a;
    asm("{ .reg .u64 t; cvta.to.shared.u64 t, %1; cvt.u32.u64 %0, t; }" : "=r"(a) : "l"(p));
    return a;
}
__device__ __forceinline__ void mma_f16(float* d, const uint32_t* a, const uint32_t* b){
    asm volatile("mma.sync.aligned.m16n8k16.row.col.f32.f16.f16.f32 "
        "{%0,%1,%2,%3}, {%4,%5,%6,%7}, {%8,%9}, {%0,%1,%2,%3};"
        : "+f"(d[0]), "+f"(d[1]), "+f"(d[2]), "+f"(d[3])
        : "r"(a[0]), "r"(a[1]), "r"(a[2]), "r"(a[3]), "r"(b[0]), "r"(b[1]));
}
__device__ __forceinline__ void cpa16(uint32_t dst, const void* src){
    asm volatile("cp.async.cg.shared.global [%0], [%1], 16;" :: "r"(dst), "l"(src));
}

// ---------------------------------------------------------------------------
__global__ __launch_bounds__(256) void cvt_h(const float* __restrict__ s,
                                             __half* __restrict__ d, int n){
    int i = blockIdx.x*256 + threadIdx.x;
    if(i<n) d[i] = __float2half(s[i]);
}

// ---------------------------------------------------------------------------
// depthwise 3x3 + residual; writes fp32 + fp16 copies (channel-major)
// ---------------------------------------------------------------------------
template<int IN_STD>
__global__ __launch_bounds__(256) void dw3_res(const float* __restrict__ x,
        const float* __restrict__ w, const float* __restrict__ b,
        float* __restrict__ out, __half* __restrict__ out16){
    int idx = blockIdx.x*256 + threadIdx.x;
    int hw = idx % 784;
    int p  = idx / 784;
    int c  = p >> 6;
    int h  = hw/28, wc = hw%28;
    const float* xp;
    if(IN_STD){
        int bimg = p & 63;
        xp = x + ((size_t)bimg*512 + c)*784;
    } else {
        xp = x + (size_t)p*784;
    }
    const float* wp = w + c*9;
    float acc = b[c];
    #pragma unroll
    for(int dy=0;dy<3;dy++){
        int hh = h + dy - 1;
        if(hh<0||hh>=28) continue;
        #pragma unroll
        for(int dx=0;dx<3;dx++){
            int ww = wc + dx - 1;
            if(ww<0||ww>=28) continue;
            acc += wp[dy*3+dx]*xp[hh*28+ww];
        }
    }
    float v = xp[hw] + acc;
    out[(size_t)p*784 + hw] = v;
    out16[(size_t)p*784 + hw] = __float2half(v);
}

// ---------------------------------------------------------------------------
// fp16 GEMM, 4-stage cp.async + ldmatrix. Out[m][n] = epi(W@In + bias)
// Block 128x128, BK=16, 8 warps (4m x 2n), warp 32x64, 2 CTAs/SM.
// smem/stage: A[128m][16k] pitch 48B (6144B) + B[16k][128n] pitch 272B (4352B)
// MODE 0: fp16-only out | 1: +Res fp32 | 2: proj merge +Res | 3: std +Res
// ---------------------------------------------------------------------------
#define STG 10496
template<int MODE>
__global__ __launch_bounds__(256, 2) void hgemm2(
        const __half* __restrict__ W16, const __half* __restrict__ In16,
        const float* __restrict__ bias, const float* __restrict__ Res,
        float* __restrict__ Out, __half* __restrict__ Out16, int K, int Nn)
{
    __shared__ __align__(128) char smem[4*STG];
    const uint32_t sbase = smem_u32(smem);
    const int tid = threadIdx.x, lane = tid&31, wid = tid>>5;
    const int bn0 = blockIdx.x*128, bm0 = blockIdx.y*128;
    const int wm0 = (wid>>1)*32, wn0 = (wid&1)*64;
    const int r = lane>>2, c = lane&3;
    const int r8 = lane&7, sel = lane>>3;

    float acc[2][8][4];
    #pragma unroll
    for(int i=0;i<2;i++)
        #pragma unroll
        for(int j=0;j<8;j++)
            #pragma unroll
            for(int q=0;q<4;q++) acc[i][j][q]=0.f;

    // per-thread copy roles
    const int am = tid>>1, ah = tid&1;              // A: row, 16B-half
    const int bk = tid>>4, bnc = tid&15;            // B: k-row, 16B-chunk
    const __half* aw = W16 + (size_t)(bm0+am)*K + ah*8;
    const __half* bw = In16 + (size_t)bk*Nn + bn0 + bnc*8;
    const uint32_t adst = am*48u + ah*16u;
    const uint32_t bdst = 6144u + bk*272u + bnc*16u;

    const int nk = K>>4;
    // prologue: stages 0..2
    #pragma unroll
    for(int s=0;s<3;s++){
        uint32_t su = sbase + s*STG;
        cpa16(su + adst, aw + s*16);
        cpa16(su + bdst, bw + (size_t)(s*16)*Nn);
        asm volatile("cp.async.commit_group;" ::: "memory");
    }

    // frag addresses (stage-relative)
    const uint32_t aoff = (uint32_t)(wm0 + r8 + (sel&1)*8)*48u + (sel>>1)*16u;
    const uint32_t boff = 6144u + (uint32_t)(r8 + (sel&1)*8)*272u
                        + (uint32_t)(wn0 + (sel>>1)*8)*2u;

    for(int it=0; it<nk; ++it){
        asm volatile("cp.async.wait_group 2;" ::: "memory");
        __syncthreads();
        if(it+3 < nk){
            uint32_t su = sbase + ((it+3)&3)*STG;
            cpa16(su + adst, aw + (it+3)*16);
            cpa16(su + bdst, bw + (size_t)((it+3)*16)*Nn);
        }
        asm volatile("cp.async.commit_group;" ::: "memory");

        const uint32_t su = sbase + (it&3)*STG;
        uint32_t af[2][4], bf[8][2];
        #pragma unroll
        for(int mi=0;mi<2;mi++){
            uint32_t a = su + aoff + mi*16*48u;
            asm volatile("ldmatrix.sync.aligned.m8n8.x4.shared.b16 {%0,%1,%2,%3}, [%4];"
                : "=r"(af[mi][0]), "=r"(af[mi][1]), "=r"(af[mi][2]), "=r"(af[mi][3])
                : "r"(a));
        }
        #pragma unroll
        for(int nip=0;nip<4;nip++){
            uint32_t a = su + boff + nip*16u*2u;
            asm volatile("ldmatrix.sync.aligned.m8n8.x4.trans.shared.b16 {%0,%1,%2,%3}, [%4];"
                : "=r"(bf[2*nip][0]), "=r"(bf[2*nip][1]),
                  "=r"(bf[2*nip+1][0]), "=r"(bf[2*nip+1][1])
                : "r"(a));
        }
        #pragma unroll
        for(int mi=0;mi<2;mi++)
            #pragma unroll
            for(int ni=0;ni<8;ni++)
                mma_f16(acc[mi][ni], af[mi], bf[ni]);
    }

    // epilogue
    #pragma unroll
    for(int mi=0;mi<2;mi++){
        int mA = bm0 + wm0 + mi*16 + r;
        float bv0 = bias[mA], bv1 = bias[mA+8];
        #pragma unroll
        for(int ni=0;ni<8;ni++){
            int n = bn0 + wn0 + ni*8 + 2*c;
            #pragma unroll
            for(int half=0; half<2; half++){
                int m = mA + half*8;
                float bv = half? bv1:bv0;
                float v0 = acc[mi][ni][half*2+0] + bv;
                float v1 = acc[mi][ni][half*2+1] + bv;
                if(MODE==0){
                    size_t o = (size_t)m*Nn + n;
                    *(__half2*)(Out16 + o) = __floats2half2_rn(hswish(v0), hswish(v1));
                } else if(MODE==1){
                    size_t o = (size_t)m*Nn + n;
                    float2 rv = *(const float2*)(Res + o);
                    float2 w2; w2.x = rv.x + v0; w2.y = rv.y + v1;
                    *(float2*)(Out + o) = w2;
                } else if(MODE==2){
                    #pragma unroll
                    for(int e=0;e<2;e++){
                        int nn = n+e; float v = e? v1:v0;
                        int win = nn/49, t = nn - win*49;
                        int bimg = win>>4, wi=(win>>2)&3, wj=win&3;
                        int r2 = t/7, c2 = t - r2*7;
                        size_t idx = ((size_t)m*64 + bimg)*784 + (wi*7+r2)*28 + wj*7+c2;
                        Out[idx] = Res[idx] + v;
                    }
                } else {
                    size_t ri = (size_t)m*Nn + n;
                    #pragma unroll
                    for(int e=0;e<2;e++){
                        int nn = n+e; float v = e? v1:v0;
                        int bimg = nn/784, hw = nn - bimg*784;
                        Out[(size_t)bimg*401408 + (size_t)m*784 + hw] = Res[ri+e] + v;
                    }
                }
            }
        }
    }
}

// ---------------------------------------------------------------------------
// Cascaded window attention; output now fp16-only (C16).
// ---------------------------------------------------------------------------
#define AP 52
#define SP_F   (64*AP)
#define Y_F    (80*AP)
#define QC_F   (49*20)
#define KT_F   (49*20)
#define ATT_F  (49*AP)
#define QW_F   (96*64)
#define ATT_SMEM_FLOATS (SP_F + Y_F + QC_F + KT_F + ATT_F + QW_F + 96)
#define ATT_SMEM_BYTES  (ATT_SMEM_FLOATS*4)

__global__ __launch_bounds__(256) void attn_kernel(
    const float* __restrict__ A,
    const float* __restrict__ qkvw, const float* __restrict__ qkvb,
    const float* __restrict__ w7, const float* __restrict__ b7,
    const float* __restrict__ w5, const float* __restrict__ b5,
    const float* __restrict__ w3, const float* __restrict__ b3,
    const float* __restrict__ abias,
    __half* __restrict__ C16)
{
    extern __shared__ float sm[];
    float* sp  = sm;
    float* y   = sp  + SP_F;
    float* qc2 = y   + Y_F;
    float* kt  = qc2 + QC_F;
    float* att = kt  + KT_F;
    float* qw  = att + ATT_F;
    float* qb  = qw  + QW_F;

    const int w = blockIdx.x, tid = threadIdx.x;
    const int bimg = w>>4, wi=(w>>2)&3, wj=w&3;
    const int off0 = (wi*7)*28 + wj*7;

    for(int hd=0; hd<8; hd++){
        for(int i=tid;i<96*64;i+=256) qw[i] = qkvw[hd*96*64 + i];
        if(tid<96) qb[tid] = qkvb[hd*96 + tid];
        for(int i=tid;i<64*49;i+=256){
            int cch = i/49, t = i - cch*49;
            int r = t/7, cc = t - r*7;
            float v = A[((size_t)(hd*64+cch)*64 + bimg)*784 + off0 + r*28 + cc];
            if(hd==0) sp[cch*AP+t] = v; else sp[cch*AP+t] += v;
        }
        __syncthreads();

        for(int u=tid; u<24*13; u+=256){
            int o0 = (u/13)*4, t0 = (u%13)*4;
            float acc[4][4];
            #pragma unroll
            for(int i=0;i<4;i++){ float bb=qb[o0+i];
                #pragma unroll
                for(int j=0;j<4;j++) acc[i][j]=bb; }
            for(int cI=0;cI<64;cI+=4){
                float4 s0=*(const float4*)&sp[(cI+0)*AP+t0];
                float4 s1=*(const float4*)&sp[(cI+1)*AP+t0];
                float4 s2=*(const float4*)&sp[(cI+2)*AP+t0];
                float4 s3=*(const float4*)&sp[(cI+3)*AP+t0];
                #pragma unroll
                for(int i=0;i<4;i++){
                    float4 qv = *(const float4*)&qw[(o0+i)*64+cI];
                    acc[i][0] += qv.x*s0.x + qv.y*s1.x + qv.z*s2.x + qv.w*s3.x;
                    acc[i][1] += qv.x*s0.y + qv.y*s1.y + qv.z*s2.y + qv.w*s3.y;
                    acc[i][2] += qv.x*s0.z + qv.y*s1.z + qv.z*s2.z + qv.w*s3.z;
                    acc[i][3] += qv.x*s0.w + qv.y*s1.w + qv.z*s2.w + qv.w*s3.w;
                }
            }
            #pragma unroll
            for(int i=0;i<4;i++)
                #pragma unroll
                for(int j=0;j<4;j++){
                    int o = o0+i, t = t0+j;
                    if(t<49){
                        float v = acc[i][j];
                        if(o<16)      y[o*AP+t] = v;
                        else if(o<32) kt[t*20 + (o-16)] = v;
                        else          y[(o-16)*AP+t] = v;
                    }
                }
        }
        __syncthreads();

        {
            int ks = (hd==0)?7:((hd==1)?5:3);
            int pad = ks>>1;
            const float* cw; const float* cb;
            if(hd==0){ cw=w7; cb=b7; }
            else if(hd==1){ cw=w5; cb=b5; }
            else { cw = w3 + (hd-2)*16*9; cb = b3 + (hd-2)*16; }
            for(int i=tid;i<16*49;i+=256){
                int ch=i/49, t=i-ch*49; int r=t/7, cc=t-r*7;
                float acc = cb[ch];
                const float* wp = cw + ch*ks*ks;
                for(int dy=0;dy<ks;dy++){
                    int rr = r+dy-pad; if(rr<0||rr>=7) continue;
                    for(int dx=0;dx<ks;dx++){
                        int c2 = cc+dx-pad; if(c2<0||c2>=7) continue;
                        acc += wp[dy*ks+dx]*y[ch*AP + rr*7+c2];
                    }
                }
                qc2[t*20+ch]=acc;
            }
        }
        __syncthreads();

        for(int i=tid;i<49*49;i+=256){
            int n=i/49, m=i-n*49;
            float acc=0.f;
            #pragma unroll
            for(int cI=0;cI<16;cI+=4){
                float4 qv=*(const float4*)&qc2[n*20+cI];
                float4 kv=*(const float4*)&kt[m*20+cI];
                acc += qv.x*kv.x+qv.y*kv.y+qv.z*kv.z+qv.w*kv.w;
            }
            int r1=n/7, c1=n-(n/7)*7, r2=m/7, c2=m-(m/7)*7;
            int dr=r1-r2; if(dr<0)dr=-dr;
            int dc=c1-c2; if(dc<0)dc=-dc;
            att[n*AP+m] = acc*0.25f + abias[hd*49 + dr*7+dc];
        }
        __syncthreads();

        if(tid<49){
            float mx=-1e30f;
            for(int m=0;m<49;m++) mx = fmaxf(mx, att[tid*AP+m]);
            float s=0.f;
            for(int m=0;m<49;m++){ float e=__expf(att[tid*AP+m]-mx); att[tid*AP+m]=e; s+=e; }
            float inv = 1.f/s;
            for(int m=0;m<49;m++) att[tid*AP+m]*=inv;
        }
        __syncthreads();

        __half* Cw = C16 + (size_t)(hd*64)*NTOT + w*49;
        for(int u=tid; u<16*13; u+=256){
            int d0=(u/13)*4, t0=(u%13)*4;
            float acc[4][4];
            #pragma unroll
            for(int i=0;i<4;i++)
                #pragma unroll
                for(int j=0;j<4;j++) acc[i][j]=0.f;
            for(int m=0;m<48;m+=4){
                float4 a0=*(const float4*)&att[(t0+0)*AP+m];
                float4 a1=*(const float4*)&att[(t0+1)*AP+m];
                float4 a2=*(const float4*)&att[(t0+2)*AP+m];
                float4 a3=*(const float4*)&att[(t0+3)*AP+m];
                #pragma unroll
                for(int i=0;i<4;i++){
                    float4 vv = *(const float4*)&y[(16+d0+i)*AP+m];
                    acc[i][0]+=vv.x*a0.x+vv.y*a0.y+vv.z*a0.z+vv.w*a0.w;
                    acc[i][1]+=vv.x*a1.x+vv.y*a1.y+vv.z*a1.z+vv.w*a1.w;
                    acc[i][2]+=vv.x*a2.x+vv.y*a2.y+vv.z*a2.z+vv.w*a2.w;
                    acc[i][3]+=vv.x*a3.x+vv.y*a3.y+vv.z*a3.z+vv.w*a3.w;
                }
            }
            {
                int m=48;
                #pragma unroll
                for(int i=0;i<4;i++){
                    float vv = y[(16+d0+i)*AP+m];
                    acc[i][0]+=vv*att[(t0+0)*AP+m];
                    acc[i][1]+=vv*att[(t0+1)*AP+m];
                    acc[i][2]+=vv*att[(t0+2)*AP+m];
                    acc[i][3]+=vv*att[(t0+3)*AP+m];
                }
            }
            #pragma unroll
            for(int i=0;i<4;i++)
                #pragma unroll
                for(int j=0;j<4;j++)
                    if(t0+j<49){
                        sp[(d0+i)*AP + t0+j] = acc[i][j];
                        Cw[(size_t)(d0+i)*NTOT + t0+j] = __float2half(hswish(acc[i][j]));
                    }
        }
        __syncthreads();
    }
}

// ---------------------------------------------------------------------------
extern "C" void kernel_launch(void* const* d_in, const int* in_sizes, int n_in,
                              void* d_out, int out_size) {
    const float* x     = (const float*)d_in[0];
    const float* dw0w  = (const float*)d_in[1];
    const float* dw0b  = (const float*)d_in[2];
    const float* f0w1  = (const float*)d_in[3];
    const float* f0b1  = (const float*)d_in[4];
    const float* f0w2  = (const float*)d_in[5];
    const float* f0b2  = (const float*)d_in[6];
    const float* qkvw  = (const float*)d_in[7];
    const float* qkvb  = (const float*)d_in[8];
    const float* w7    = (const float*)d_in[9];
    const float* b7    = (const float*)d_in[10];
    const float* w5    = (const float*)d_in[11];
    const float* b5    = (const float*)d_in[12];
    const float* w3    = (const float*)d_in[13];
    const float* b3    = (const float*)d_in[14];
    const float* ab    = (const float*)d_in[15];
    const float* pw_   = (const float*)d_in[16];
    const float* pb    = (const float*)d_in[17];
    const float* dw1w  = (const float*)d_in[18];
    const float* dw1b  = (const float*)d_in[19];
    const float* f1w1  = (const float*)d_in[20];
    const float* f1b1  = (const float*)d_in[21];
    const float* f1w2  = (const float*)d_in[22];
    const float* f1b2  = (const float*)d_in[23];
    float* out = (float*)d_out;

    float *A, *C;
    __half *A16, *C16, *H16, *W16;
    cudaGetSymbolAddress((void**)&A,   g_A);
    cudaGetSymbolAddress((void**)&C,   g_C);
    cudaGetSymbolAddress((void**)&A16, g_A16);
    cudaGetSymbolAddress((void**)&C16, g_C16);
    cudaGetSymbolAddress((void**)&H16, g_H16);
    cudaGetSymbolAddress((void**)&W16, g_W16);

    __half* w0 = W16;              // f0w1 1024x512
    __half* w1 = W16 + 524288;     // f0w2 512x1024
    __half* w2 = W16 + 1048576;    // pw   512x512
    __half* w3h= W16 + 1310720;    // f1w1 1024x512
    __half* w4 = W16 + 1835008;    // f1w2 512x1024

    cudaFuncSetAttribute(attn_kernel,
        cudaFuncAttributeMaxDynamicSharedMemorySize, ATT_SMEM_BYTES);

    // weight conversions
    cvt_h<<<2048, 256>>>(f0w1, w0, 524288);
    cvt_h<<<2048, 256>>>(f0w2, w1, 524288);
    cvt_h<<<1024, 256>>>(pw_,  w2, 262144);
    cvt_h<<<2048, 256>>>(f1w1, w3h, 524288);
    cvt_h<<<2048, 256>>>(f1w2, w4, 524288);

    // 1. A = x + dw0(x)  (fp32 + fp16)
    dw3_res<1><<<XN/256, 256>>>(x, dw0w, dw0b, A, A16);
    // 2. H16 = hswish(W1 @ A16 + b1)          M=1024 K=512
    hgemm2<0><<<dim3(NTOT/128, 8), 256>>>(w0, A16, f0b1, nullptr, nullptr, H16, 512, NTOT);
    // 3. A = A + (W2 @ H16 + b2)              M=512 K=1024
    hgemm2<1><<<dim3(NTOT/128, 4), 256>>>(w1, H16, f0b2, A, A, nullptr, 1024, NTOT);
    // 4. attention -> C16 = hswish(concat)
    attn_kernel<<<1024, 256, ATT_SMEM_BYTES>>>(A, qkvw, qkvb, w7,b7, w5,b5, w3,b3, ab, C16);
    // 5. A += merge(proj @ C16 + pb)          M=512 K=512
    hgemm2<2><<<dim3(NTOT/128, 4), 256>>>(w2, C16, pb, A, A, nullptr, 512, NTOT);
    // 6. C = A + dw1(A)  (fp32 + fp16)
    dw3_res<0><<<XN/256, 256>>>(A, dw1w, dw1b, C, C16);
    // 7. H16 = hswish(W1' @ C16 + b1')        M=1024 K=512
    hgemm2<0><<<dim3(NTOT/128, 8), 256>>>(w3h, C16, f1b1, nullptr, nullptr, H16, 512, NTOT);
    // 8. out = C + (W2' @ H16 + b2')          M=512 K=1024, std layout
    hgemm2<3><<<dim3(NTOT/128, 4), 256>>>(w4, H16, f1b2, C, out, nullptr, 1024, NTOT);
}